// round 2
// baseline (speedup 1.0000x reference)
#include <cuda_runtime.h>
#include <cstdint>

#define B_    4
#define N_    2048
#define DIM_  1536
#define H_    16
#define DH_   96
#define QKV3  4608      // 3*H*DH
#define HDH   1536      // H*DH
#define SCALE_ 0.10206207261596575f  // 96^-0.5

// ---------------- scratch (no allocations allowed) ----------------
__device__ float g_qkv[(size_t)B_ * N_ * QKV3];      // 151 MB
__device__ float g_q  [(size_t)B_ * H_ * N_ * DH_];  // 50 MB
__device__ float g_k  [(size_t)B_ * H_ * N_ * DH_];
__device__ float g_v  [(size_t)B_ * H_ * N_ * DH_];
__device__ float g_ctx[(size_t)B_ * N_ * HDH];       // 50 MB

// ---------------- SGEMM: C[M,N] = A[M,K] @ B[K,N] (+bias) --------
// 128x128 block tile, BK=8, 256 threads, 8x8 per-thread microtile.
// M,N divisible by 128; K divisible by 8; all rows 16B-aligned.
__global__ void sgemm128(const float* __restrict__ A, const float* __restrict__ B,
                         const float* __restrict__ bias, float* __restrict__ C,
                         int M, int N, int K) {
    __shared__ float As[8][128];
    __shared__ float Bs[8][128];

    const int tid  = threadIdx.x;
    const int brow = blockIdx.y * 128;
    const int bcol = blockIdx.x * 128;

    const int a_row = tid >> 1;
    const int a_k   = (tid & 1) * 4;
    const int b_k   = tid >> 5;
    const int b_col = (tid & 31) * 4;

    const int ty = tid >> 4;   // 0..15
    const int tx = tid & 15;   // 0..15

    float acc[8][8];
#pragma unroll
    for (int i = 0; i < 8; i++)
#pragma unroll
        for (int j = 0; j < 8; j++) acc[i][j] = 0.f;

    for (int k0 = 0; k0 < K; k0 += 8) {
        float4 av = *(const float4*)(A + (size_t)(brow + a_row) * K + k0 + a_k);
        As[a_k + 0][a_row] = av.x;
        As[a_k + 1][a_row] = av.y;
        As[a_k + 2][a_row] = av.z;
        As[a_k + 3][a_row] = av.w;
        *(float4*)(&Bs[b_k][b_col]) =
            *(const float4*)(B + (size_t)(k0 + b_k) * N + bcol + b_col);
        __syncthreads();

#pragma unroll
        for (int kk = 0; kk < 8; kk++) {
            float ar[8], br[8];
            *(float4*)(ar)     = *(const float4*)(&As[kk][ty * 8]);
            *(float4*)(ar + 4) = *(const float4*)(&As[kk][ty * 8 + 4]);
            *(float4*)(br)     = *(const float4*)(&Bs[kk][tx * 8]);
            *(float4*)(br + 4) = *(const float4*)(&Bs[kk][tx * 8 + 4]);
#pragma unroll
            for (int i = 0; i < 8; i++)
#pragma unroll
                for (int j = 0; j < 8; j++) acc[i][j] += ar[i] * br[j];
        }
        __syncthreads();
    }

#pragma unroll
    for (int i = 0; i < 8; i++) {
        const int r = brow + ty * 8 + i;
#pragma unroll
        for (int j = 0; j < 8; j += 4) {
            const int c = bcol + tx * 8 + j;
            float4 v = make_float4(acc[i][j], acc[i][j + 1], acc[i][j + 2], acc[i][j + 3]);
            if (bias) {
                v.x += bias[c];     v.y += bias[c + 1];
                v.z += bias[c + 2]; v.w += bias[c + 3];
            }
            *(float4*)(C + (size_t)r * N + c) = v;
        }
    }
}

// ---------------- RoPE + transpose to [B,H,N,DH] ------------------
// which=0: q (rope), 1: k (rope), 2: v (copy)
__global__ void rope_kernel(const float* __restrict__ f1,
                            const float* __restrict__ f2,
                            const float* __restrict__ f3) {
    const int per = B_ * H_ * N_ * DH_;
    int idx = blockIdx.x * blockDim.x + threadIdx.x;
    if (idx >= 3 * per) return;
    const int which = idx / per;
    int r = idx - which * per;
    const int d = r % DH_;  r /= DH_;
    const int n = r % N_;   r /= N_;
    const int h = r % H_;
    const int b = r / H_;

    const size_t src_row = (size_t)(b * N_ + n) * QKV3;
    const int base = which * HDH + h * DH_;
    const float t = g_qkv[src_row + base + d];

    float outv;
    if (which == 2) {
        outv = t;
    } else {
        const int c = d >> 5;        // 32-wide chunk
        const int j = d & 31;
        const float* f = (c == 0) ? f1 : ((c == 1) ? f2 : f3);
        const float fr = f[n * 32 + j];
        float rot;
        if (j < 16) rot = -g_qkv[src_row + base + c * 32 + j + 16];
        else        rot =  g_qkv[src_row + base + c * 32 + j - 16];
        outv = t * __cosf(fr) + rot * __sinf(fr);
    }
    float* dst = (which == 0) ? g_q : ((which == 1) ? g_k : g_v);
    dst[(size_t)((b * H_ + h) * N_ + n) * DH_ + d] = outv;
}

// ---------------- Flash attention (fp32, online softmax) ---------
#define BM 64
#define BN 64
#define QK_PAD 68    // padded m/n row length for transposed Q/K tiles
#define V_PAD  104   // padded d row length for V tile
#define S_PAD  65

#define FLASH_SMEM_FLOATS (DH_*QK_PAD*2 + BN*V_PAD + BM*S_PAD + 3*BM)
#define FLASH_SMEM_BYTES  (FLASH_SMEM_FLOATS * 4)

__global__ void flash_kernel() {
    extern __shared__ float sm[];
    float* Qt  = sm;                       // [DH_][QK_PAD]  (k-major)
    float* Kt  = Qt + DH_ * QK_PAD;        // [DH_][QK_PAD]
    float* Vs  = Kt + DH_ * QK_PAD;        // [BN][V_PAD]
    float* Ss  = Vs + BN * V_PAD;          // [BM][S_PAD]
    float* m_s = Ss + BM * S_PAD;          // [BM]
    float* l_s = m_s + BM;
    float* c_s = l_s + BM;

    const int tid = threadIdx.x;           // 256 threads
    const int bh  = blockIdx.y;            // b*H + h
    const int b   = bh >> 4;
    const int h   = bh & 15;
    const int m0  = blockIdx.x * BM;

    const float* Qg = g_q + ((size_t)bh * N_ + m0) * DH_;
    const float* Kg = g_k + (size_t)bh * N_ * DH_;
    const float* Vg = g_v + (size_t)bh * N_ * DH_;

    // load Q tile transposed: Qt[d][m]
    for (int i = tid; i < BM * DH_ / 4; i += 256) {
        const int e = i * 4;
        const int m = e / DH_, d = e % DH_;
        const float4 v = *(const float4*)(Qg + e);
        Qt[(d + 0) * QK_PAD + m] = v.x;
        Qt[(d + 1) * QK_PAD + m] = v.y;
        Qt[(d + 2) * QK_PAD + m] = v.z;
        Qt[(d + 3) * QK_PAD + m] = v.w;
    }
    if (tid < BM) { m_s[tid] = -1e30f; l_s[tid] = 0.f; }

    const int om = tid >> 2;          // query row owned for O accumulation
    const int od = (tid & 3) * 24;    // dim offset (24 dims per thread)
    float acc[24];
#pragma unroll
    for (int i = 0; i < 24; i++) acc[i] = 0.f;

    __syncthreads();

    for (int n0 = 0; n0 < N_; n0 += BN) {
        // load K (transposed) and V tiles
        for (int i = tid; i < BN * DH_ / 4; i += 256) {
            const int e = i * 4;
            const int n = e / DH_, d = e % DH_;
            const float4 kv = *(const float4*)(Kg + (size_t)n0 * DH_ + e);
            Kt[(d + 0) * QK_PAD + n] = kv.x;
            Kt[(d + 1) * QK_PAD + n] = kv.y;
            Kt[(d + 2) * QK_PAD + n] = kv.z;
            Kt[(d + 3) * QK_PAD + n] = kv.w;
            *(float4*)(Vs + n * V_PAD + d) = *(const float4*)(Vg + (size_t)n0 * DH_ + e);
        }
        __syncthreads();

        // S = Q @ K^T * scale  (16x16 threads, 4x4 microtile)
        {
            const int ty = tid >> 4, tx = tid & 15;
            const int rm = ty * 4, rn = tx * 4;
            float s[4][4];
#pragma unroll
            for (int i = 0; i < 4; i++)
#pragma unroll
                for (int j = 0; j < 4; j++) s[i][j] = 0.f;

            for (int k = 0; k < DH_; k++) {
                const float4 a = *(const float4*)(Qt + k * QK_PAD + rm);
                const float4 bb = *(const float4*)(Kt + k * QK_PAD + rn);
                const float av[4] = {a.x, a.y, a.z, a.w};
                const float bv[4] = {bb.x, bb.y, bb.z, bb.w};
#pragma unroll
                for (int i = 0; i < 4; i++)
#pragma unroll
                    for (int j = 0; j < 4; j++) s[i][j] += av[i] * bv[j];
            }
#pragma unroll
            for (int i = 0; i < 4; i++)
#pragma unroll
                for (int j = 0; j < 4; j++)
                    Ss[(rm + i) * S_PAD + rn + j] = s[i][j] * SCALE_;
        }
        __syncthreads();

        // online softmax, one thread per query row
        if (tid < BM) {
            float* srow = Ss + tid * S_PAD;
            const float mold = m_s[tid];
            float mx = mold;
#pragma unroll 8
            for (int j = 0; j < BN; j++) mx = fmaxf(mx, srow[j]);
            const float corr = __expf(mold - mx);
            float lsum = 0.f;
#pragma unroll 8
            for (int j = 0; j < BN; j++) {
                const float p = __expf(srow[j] - mx);
                srow[j] = p;
                lsum += p;
            }
            m_s[tid] = mx;
            l_s[tid] = l_s[tid] * corr + lsum;
            c_s[tid] = corr;
        }
        __syncthreads();

        // O = O*corr + P @ V
        {
            const float corr = c_s[om];
#pragma unroll
            for (int i = 0; i < 24; i++) acc[i] *= corr;
            const float* srow = Ss + om * S_PAD;
            for (int j = 0; j < BN; j++) {
                const float p = srow[j];
                const float4* vp = (const float4*)(Vs + j * V_PAD + od);
#pragma unroll
                for (int i = 0; i < 6; i++) {
                    const float4 v = vp[i];
                    acc[i * 4 + 0] += p * v.x;
                    acc[i * 4 + 1] += p * v.y;
                    acc[i * 4 + 2] += p * v.z;
                    acc[i * 4 + 3] += p * v.w;
                }
            }
        }
        __syncthreads();
    }

    // normalize + write to ctx[b, n, h*DH + d]
    const float inv = 1.f / l_s[om];
    const int n = m0 + om;
    float* outp = g_ctx + (size_t)(b * N_ + n) * HDH + h * DH_ + od;
#pragma unroll
    for (int i = 0; i < 6; i++) {
        *(float4*)(outp + i * 4) = make_float4(acc[i * 4 + 0] * inv, acc[i * 4 + 1] * inv,
                                               acc[i * 4 + 2] * inv, acc[i * 4 + 3] * inv);
    }
}

// ------------------------------------------------------------------
extern "C" void kernel_launch(void* const* d_in, const int* in_sizes, int n_in,
                              void* d_out, int out_size) {
    const float* x    = (const float*)d_in[0];
    const float* f1   = (const float*)d_in[1];
    const float* f2   = (const float*)d_in[2];
    const float* f3   = (const float*)d_in[3];
    const float* Wqkv = (const float*)d_in[4];
    const float* Wout = (const float*)d_in[5];
    const float* bout = (const float*)d_in[6];
    float* out = (float*)d_out;

    // device scratch pointers (symbols referenced directly by kernels;
    // we still need raw pointers for the reusable sgemm)
    float* qkv; cudaGetSymbolAddress((void**)&qkv, g_qkv);
    float* ctx; cudaGetSymbolAddress((void**)&ctx, g_ctx);

    const int M = B_ * N_;   // 8192

    // 1) QKV GEMM: [8192,1536] @ [1536,4608]
    {
        dim3 grid(QKV3 / 128, M / 128);
        sgemm128<<<grid, 256>>>(x, Wqkv, nullptr, qkv, M, QKV3, DIM_);
    }

    // 2) RoPE + head transpose
    {
        const int total = 3 * B_ * H_ * N_ * DH_;   // divisible by 256
        rope_kernel<<<total / 256, 256>>>(f1, f2, f3);
    }

    // 3) Flash attention
    {
        static int smem_set = 0;
        if (!smem_set) {
            cudaFuncSetAttribute(flash_kernel, cudaFuncAttributeMaxDynamicSharedMemorySize,
                                 FLASH_SMEM_BYTES);
            smem_set = 1;
        }
        dim3 grid(N_ / BM, B_ * H_);
        flash_kernel<<<grid, 256, FLASH_SMEM_BYTES>>>();
    }

    // 4) Output GEMM + bias: [8192,1536] @ [1536,1536]
    {
        dim3 grid(HDH / 128, M / 128);
        sgemm128<<<grid, 256>>>(ctx, Wout, bout, out, M, HDH, HDH);
    }
}

// round 4
// speedup vs baseline: 1.2814x; 1.2814x over previous
#include <cuda_runtime.h>
#include <cuda_bf16.h>
#include <cstdint>

#define B_    4
#define N_    2048
#define DIM_  1536
#define H_    16
#define DH_   96
#define QKV3  4608      // 3*H*DH
#define HDH   1536      // H*DH
#define M_    (B_*N_)   // 8192
#define SCALE_ 0.10206207261596575f  // 96^-0.5

// ---------------- scratch (no allocations allowed) ----------------
__device__ float g_qkv[(size_t)M_ * QKV3];           // 151 MB
__device__ float g_q  [(size_t)B_ * H_ * N_ * DH_];  // 50 MB
__device__ float g_k  [(size_t)B_ * H_ * N_ * DH_];
__device__ float g_v  [(size_t)B_ * H_ * N_ * DH_];
__device__ float g_ctx[(size_t)M_ * HDH];            // 50 MB

__device__ __nv_bfloat16 g_xhi[(size_t)M_ * DIM_];   // 25 MB each
__device__ __nv_bfloat16 g_xlo[(size_t)M_ * DIM_];
__device__ __nv_bfloat16 g_chi[(size_t)M_ * HDH];
__device__ __nv_bfloat16 g_clo[(size_t)M_ * HDH];
__device__ __nv_bfloat16 g_wqh[(size_t)QKV3 * DIM_]; // W^T [N,K]
__device__ __nv_bfloat16 g_wql[(size_t)QKV3 * DIM_];
__device__ __nv_bfloat16 g_woh[(size_t)HDH * HDH];
__device__ __nv_bfloat16 g_wol[(size_t)HDH * HDH];

// ================= helpers (sm_80+ only: cp.async, mma.sync) ======
__device__ __forceinline__ uint32_t smem_u32(const void* p) {
    uint32_t a;
    asm("{ .reg .u64 t; cvta.to.shared.u64 t, %1; cvt.u32.u64 %0, t; }"
        : "=r"(a) : "l"(p));
    return a;
}
__device__ __forceinline__ uint32_t lds32(uint32_t a) {
    uint32_t v;
    asm volatile("ld.shared.b32 %0, [%1];" : "=r"(v) : "r"(a));
    return v;
}
#define CP_ASYNC16(saddr, gptr) \
    asm volatile("cp.async.cg.shared.global [%0], [%1], 16;" :: "r"(saddr), "l"(gptr))
#define CP_COMMIT() asm volatile("cp.async.commit_group;" ::: "memory")
#define CP_WAIT(n)  asm volatile("cp.async.wait_group %0;" :: "n"(n) : "memory")

__device__ __forceinline__ void mma_bf16(float* c, const uint32_t* a, const uint32_t* b) {
    asm volatile(
        "mma.sync.aligned.m16n8k16.row.col.f32.bf16.bf16.f32 "
        "{%0,%1,%2,%3}, {%4,%5,%6,%7}, {%8,%9}, {%0,%1,%2,%3};"
        : "+f"(c[0]), "+f"(c[1]), "+f"(c[2]), "+f"(c[3])
        : "r"(a[0]), "r"(a[1]), "r"(a[2]), "r"(a[3]), "r"(b[0]), "r"(b[1]));
}

// ====== split-bf16 mma.sync GEMM: C[M,N] = A@W (+bias) ============
// A hi/lo [M,K] bf16 row-major; W^T hi/lo [N,K] bf16 row-major (both K-major).
// CTA 128x128, BK=32, 256 threads (8 warps, warp tile 32x64).
// smem tile row stride 40 bf16 (80 B) -> fragment LDS bank = (20r+tg)%32, conflict-free.
#define GS_STRIDE 80            // bytes per smem row (32 bf16 + 8 pad)
#define GS_TILE   10240         // 128 rows * 80 B
#define GS_STAGE  40960         // Ahi, Alo, Bhi, Blo tiles
#define GEMM_SMEM (2 * GS_STAGE)

__global__ void __launch_bounds__(256, 1)
gemm_mma(const __nv_bfloat16* __restrict__ Ahi, const __nv_bfloat16* __restrict__ Alo,
         const __nv_bfloat16* __restrict__ Bhi, const __nv_bfloat16* __restrict__ Blo,
         const float* __restrict__ bias, float* __restrict__ C, int N, int K) {
    extern __shared__ char sm_[];
    const uint32_t sb = smem_u32(sm_);
    const int tid = threadIdx.x;
    const int wid = tid >> 5, lane = tid & 31;
    const int g = lane >> 2, tg = lane & 3;     // mma group / thread-in-group
    const int wm = wid & 3, wn = wid >> 2;      // warp grid 4x2
    const int brow = blockIdx.y * 128;
    const int bcol = blockIdx.x * 128;

    float acc[2][8][4];
#pragma unroll
    for (int mt = 0; mt < 2; mt++)
#pragma unroll
        for (int nt = 0; nt < 8; nt++)
#pragma unroll
            for (int i = 0; i < 4; i++) acc[mt][nt][i] = 0.f;

    const char* gsrc0 = (const char*)Ahi;
    const char* gsrc1 = (const char*)Alo;
    const char* gsrc2 = (const char*)Bhi;
    const char* gsrc3 = (const char*)Blo;

    const int nst = K / 32;

    // ---- stage loader: 4 tiles x 128 rows x 2 chunks(16B of data)/thread ----
    auto load_stage = [&](int s) {
        const uint32_t base = sb + (uint32_t)(s & 1) * GS_STAGE;
        const int k0 = s * 32;
#pragma unroll
        for (int j = 0; j < 2; j++) {
            const int idx = tid * 2 + j;        // 0..511
            const int r = idx >> 2, c = idx & 3;
            const uint32_t so = (uint32_t)r * GS_STRIDE + (uint32_t)c * 16;
            const size_t goA = ((size_t)(brow + r) * K + k0 + c * 8) * 2;
            const size_t goB = ((size_t)(bcol + r) * K + k0 + c * 8) * 2;
            CP_ASYNC16(base + so,                gsrc0 + goA);
            CP_ASYNC16(base + GS_TILE + so,      gsrc1 + goA);
            CP_ASYNC16(base + 2 * GS_TILE + so,  gsrc2 + goB);
            CP_ASYNC16(base + 3 * GS_TILE + so,  gsrc3 + goB);
        }
    };

    load_stage(0); CP_COMMIT();

    for (int s = 0; s < nst; s++) {
        if (s + 1 < nst) { load_stage(s + 1); CP_COMMIT(); CP_WAIT(1); }
        else             { CP_WAIT(0); }
        __syncthreads();

        const uint32_t base = sb + (uint32_t)(s & 1) * GS_STAGE;
#pragma unroll
        for (int kk = 0; kk < 2; kk++) {
            const uint32_t colb = (uint32_t)(kk * 16 + tg * 2) * 2;
            uint32_t ah[2][4], al[2][4], bh[8][2], bl[8][2];
#pragma unroll
            for (int mt = 0; mt < 2; mt++) {
                const uint32_t r0 = (uint32_t)(wm * 32 + mt * 16 + g);
                const uint32_t o0 = base + r0 * GS_STRIDE + colb;
                const uint32_t o1 = base + (r0 + 8) * GS_STRIDE + colb;
                ah[mt][0] = lds32(o0);
                ah[mt][1] = lds32(o1);
                ah[mt][2] = lds32(o0 + 16);
                ah[mt][3] = lds32(o1 + 16);
                al[mt][0] = lds32(o0 + GS_TILE);
                al[mt][1] = lds32(o1 + GS_TILE);
                al[mt][2] = lds32(o0 + GS_TILE + 16);
                al[mt][3] = lds32(o1 + GS_TILE + 16);
            }
#pragma unroll
            for (int nt = 0; nt < 8; nt++) {
                const uint32_t n0 = (uint32_t)(wn * 64 + nt * 8 + g);
                const uint32_t ob = base + 2 * GS_TILE + n0 * GS_STRIDE + colb;
                bh[nt][0] = lds32(ob);
                bh[nt][1] = lds32(ob + 16);
                bl[nt][0] = lds32(ob + GS_TILE);
                bl[nt][1] = lds32(ob + GS_TILE + 16);
            }
#pragma unroll
            for (int mt = 0; mt < 2; mt++)
#pragma unroll
                for (int nt = 0; nt < 8; nt++) {
                    mma_bf16(acc[mt][nt], ah[mt], bh[nt]);
                    mma_bf16(acc[mt][nt], ah[mt], bl[nt]);
                    mma_bf16(acc[mt][nt], al[mt], bh[nt]);
                }
        }
        __syncthreads();
    }

    // ---- epilogue: direct register writeout (+bias) ----
#pragma unroll
    for (int mt = 0; mt < 2; mt++) {
        const int r0 = brow + wm * 32 + mt * 16 + g;
#pragma unroll
        for (int nt = 0; nt < 8; nt++) {
            const int c = bcol + wn * 64 + nt * 8 + tg * 2;
            float2 v0 = make_float2(acc[mt][nt][0], acc[mt][nt][1]);
            float2 v1 = make_float2(acc[mt][nt][2], acc[mt][nt][3]);
            if (bias) {
                const float b0 = bias[c], b1 = bias[c + 1];
                v0.x += b0; v0.y += b1; v1.x += b0; v1.y += b1;
            }
            *(float2*)(C + (size_t)r0 * N + c)       = v0;
            *(float2*)(C + (size_t)(r0 + 8) * N + c) = v1;
        }
    }
}

// ---------------- hi/lo conversion kernels ------------------------
__global__ void cvt_hilo(const float* __restrict__ src,
                         __nv_bfloat16* __restrict__ hi,
                         __nv_bfloat16* __restrict__ lo, int n4) {
    const int i = blockIdx.x * blockDim.x + threadIdx.x;
    if (i >= n4) return;
    const float4 v = ((const float4*)src)[i];
    float h0 = __bfloat162float(__float2bfloat16(v.x));
    float h1 = __bfloat162float(__float2bfloat16(v.y));
    float h2 = __bfloat162float(__float2bfloat16(v.z));
    float h3 = __bfloat162float(__float2bfloat16(v.w));
    ((__nv_bfloat162*)hi)[i * 2]     = __floats2bfloat162_rn(v.x, v.y);
    ((__nv_bfloat162*)hi)[i * 2 + 1] = __floats2bfloat162_rn(v.z, v.w);
    ((__nv_bfloat162*)lo)[i * 2]     = __floats2bfloat162_rn(v.x - h0, v.y - h1);
    ((__nv_bfloat162*)lo)[i * 2 + 1] = __floats2bfloat162_rn(v.z - h2, v.w - h3);
}

// W [K,N] row-major -> W^T hi/lo [N,K] row-major
__global__ void transpose_hilo(const float* __restrict__ W,
                               __nv_bfloat16* __restrict__ hi,
                               __nv_bfloat16* __restrict__ lo, int K, int N) {
    __shared__ float t[32][33];
    const int n0 = blockIdx.x * 32, k0 = blockIdx.y * 32;
    const int tx = threadIdx.x;
    for (int y = threadIdx.y; y < 32; y += 8)
        t[y][tx] = W[(size_t)(k0 + y) * N + n0 + tx];
    __syncthreads();
    for (int y = threadIdx.y; y < 32; y += 8) {
        const float v = t[tx][y];          // = W[k0+tx][n0+y]
        const __nv_bfloat16 h = __float2bfloat16(v);
        const size_t o = (size_t)(n0 + y) * K + k0 + tx;
        hi[o] = h;
        lo[o] = __float2bfloat16(v - __bfloat162float(h));
    }
}

// ---------------- RoPE + transpose to [B,H,N,DH] ------------------
__global__ void rope_kernel(const float* __restrict__ f1,
                            const float* __restrict__ f2,
                            const float* __restrict__ f3) {
    const int per = B_ * H_ * N_ * DH_;
    int idx = blockIdx.x * blockDim.x + threadIdx.x;
    if (idx >= 3 * per) return;
    const int which = idx / per;
    int r = idx - which * per;
    const int d = r % DH_;  r /= DH_;
    const int n = r % N_;   r /= N_;
    const int h = r % H_;
    const int b = r / H_;

    const size_t src_row = (size_t)(b * N_ + n) * QKV3;
    const int base = which * HDH + h * DH_;
    const float t = g_qkv[src_row + base + d];

    float outv;
    if (which == 2) {
        outv = t;
    } else {
        const int c = d >> 5;
        const int j = d & 31;
        const float* f = (c == 0) ? f1 : ((c == 1) ? f2 : f3);
        const float fr = f[n * 32 + j];
        float rot;
        if (j < 16) rot = -g_qkv[src_row + base + c * 32 + j + 16];
        else        rot =  g_qkv[src_row + base + c * 32 + j - 16];
        outv = t * __cosf(fr) + rot * __sinf(fr);
    }
    float* dst = (which == 0) ? g_q : ((which == 1) ? g_k : g_v);
    dst[(size_t)((b * H_ + h) * N_ + n) * DH_ + d] = outv;
}

// ---------------- Flash attention (fp32, online softmax) ---------
#define BM 64
#define BN 64
#define QK_PAD 68
#define V_PAD  104
#define S_PAD  65
#define FLASH_SMEM_FLOATS (DH_*QK_PAD*2 + BN*V_PAD + BM*S_PAD + 3*BM)
#define FLASH_SMEM_BYTES  (FLASH_SMEM_FLOATS * 4)

__global__ void flash_kernel() {
    extern __shared__ float sm[];
    float* Qt  = sm;
    float* Kt  = Qt + DH_ * QK_PAD;
    float* Vs  = Kt + DH_ * QK_PAD;
    float* Ss  = Vs + BN * V_PAD;
    float* m_s = Ss + BM * S_PAD;
    float* l_s = m_s + BM;
    float* c_s = l_s + BM;

    const int tid = threadIdx.x;
    const int bh  = blockIdx.y;
    const int b   = bh >> 4;
    const int h   = bh & 15;
    const int m0  = blockIdx.x * BM;

    const float* Qg = g_q + ((size_t)bh * N_ + m0) * DH_;
    const float* Kg = g_k + (size_t)bh * N_ * DH_;
    const float* Vg = g_v + (size_t)bh * N_ * DH_;

    for (int i = tid; i < BM * DH_ / 4; i += 256) {
        const int e = i * 4;
        const int m = e / DH_, d = e % DH_;
        const float4 v = *(const float4*)(Qg + e);
        Qt[(d + 0) * QK_PAD + m] = v.x;
        Qt[(d + 1) * QK_PAD + m] = v.y;
        Qt[(d + 2) * QK_PAD + m] = v.z;
        Qt[(d + 3) * QK_PAD + m] = v.w;
    }
    if (tid < BM) { m_s[tid] = -1e30f; l_s[tid] = 0.f; }

    const int om = tid >> 2;
    const int od = (tid & 3) * 24;
    float acc[24];
#pragma unroll
    for (int i = 0; i < 24; i++) acc[i] = 0.f;

    __syncthreads();

    for (int n0 = 0; n0 < N_; n0 += BN) {
        for (int i = tid; i < BN * DH_ / 4; i += 256) {
            const int e = i * 4;
            const int n = e / DH_, d = e % DH_;
            const float4 kv = *(const float4*)(Kg + (size_t)n0 * DH_ + e);
            Kt[(d + 0) * QK_PAD + n] = kv.x;
            Kt[(d + 1) * QK_PAD + n] = kv.y;
            Kt[(d + 2) * QK_PAD + n] = kv.z;
            Kt[(d + 3) * QK_PAD + n] = kv.w;
            *(float4*)(Vs + n * V_PAD + d) = *(const float4*)(Vg + (size_t)n0 * DH_ + e);
        }
        __syncthreads();

        {
            const int ty = tid >> 4, tx = tid & 15;
            const int rm = ty * 4, rn = tx * 4;
            float s[4][4];
#pragma unroll
            for (int i = 0; i < 4; i++)
#pragma unroll
                for (int j = 0; j < 4; j++) s[i][j] = 0.f;

            for (int k = 0; k < DH_; k++) {
                const float4 a = *(const float4*)(Qt + k * QK_PAD + rm);
                const float4 bb = *(const float4*)(Kt + k * QK_PAD + rn);
                const float av[4] = {a.x, a.y, a.z, a.w};
                const float bv[4] = {bb.x, bb.y, bb.z, bb.w};
#pragma unroll
                for (int i = 0; i < 4; i++)
#pragma unroll
                    for (int j = 0; j < 4; j++) s[i][j] += av[i] * bv[j];
            }
#pragma unroll
            for (int i = 0; i < 4; i++)
#pragma unroll
                for (int j = 0; j < 4; j++)
                    Ss[(rm + i) * S_PAD + rn + j] = s[i][j] * SCALE_;
        }
        __syncthreads();

        if (tid < BM) {
            float* srow = Ss + tid * S_PAD;
            const float mold = m_s[tid];
            float mx = mold;
#pragma unroll 8
            for (int j = 0; j < BN; j++) mx = fmaxf(mx, srow[j]);
            const float corr = __expf(mold - mx);
            float lsum = 0.f;
#pragma unroll 8
            for (int j = 0; j < BN; j++) {
                const float p = __expf(srow[j] - mx);
                srow[j] = p;
                lsum += p;
            }
            m_s[tid] = mx;
            l_s[tid] = l_s[tid] * corr + lsum;
            c_s[tid] = corr;
        }
        __syncthreads();

        {
            const float corr = c_s[om];
#pragma unroll
            for (int i = 0; i < 24; i++) acc[i] *= corr;
            const float* srow = Ss + om * S_PAD;
            for (int j = 0; j < BN; j++) {
                const float p = srow[j];
                const float4* vp = (const float4*)(Vs + j * V_PAD + od);
#pragma unroll
                for (int i = 0; i < 6; i++) {
                    const float4 v = vp[i];
                    acc[i * 4 + 0] += p * v.x;
                    acc[i * 4 + 1] += p * v.y;
                    acc[i * 4 + 2] += p * v.z;
                    acc[i * 4 + 3] += p * v.w;
                }
            }
        }
        __syncthreads();
    }

    const float inv = 1.f / l_s[om];
    const int n = m0 + om;
    float* outp = g_ctx + (size_t)(b * N_ + n) * HDH + h * DH_ + od;
#pragma unroll
    for (int i = 0; i < 6; i++) {
        *(float4*)(outp + i * 4) = make_float4(acc[i * 4 + 0] * inv, acc[i * 4 + 1] * inv,
                                               acc[i * 4 + 2] * inv, acc[i * 4 + 3] * inv);
    }
}

// ------------------------------------------------------------------
extern "C" void kernel_launch(void* const* d_in, const int* in_sizes, int n_in,
                              void* d_out, int out_size) {
    const float* x    = (const float*)d_in[0];
    const float* f1   = (const float*)d_in[1];
    const float* f2   = (const float*)d_in[2];
    const float* f3   = (const float*)d_in[3];
    const float* Wqkv = (const float*)d_in[4];
    const float* Wout = (const float*)d_in[5];
    const float* bout = (const float*)d_in[6];
    float* out = (float*)d_out;

    float *qkv, *ctx;
    __nv_bfloat16 *xhi, *xlo, *chi, *clo, *wqh, *wql, *woh, *wol;
    cudaGetSymbolAddress((void**)&qkv, g_qkv);
    cudaGetSymbolAddress((void**)&ctx, g_ctx);
    cudaGetSymbolAddress((void**)&xhi, g_xhi);
    cudaGetSymbolAddress((void**)&xlo, g_xlo);
    cudaGetSymbolAddress((void**)&chi, g_chi);
    cudaGetSymbolAddress((void**)&clo, g_clo);
    cudaGetSymbolAddress((void**)&wqh, g_wqh);
    cudaGetSymbolAddress((void**)&wql, g_wql);
    cudaGetSymbolAddress((void**)&woh, g_woh);
    cudaGetSymbolAddress((void**)&wol, g_wol);

    cudaFuncSetAttribute(gemm_mma, cudaFuncAttributeMaxDynamicSharedMemorySize, GEMM_SMEM);
    cudaFuncSetAttribute(flash_kernel, cudaFuncAttributeMaxDynamicSharedMemorySize,
                         FLASH_SMEM_BYTES);

    // 1) convert x -> hi/lo bf16; transpose+convert weights
    cvt_hilo<<<(M_ * DIM_ / 4 + 255) / 256, 256>>>(x, xhi, xlo, M_ * DIM_ / 4);
    transpose_hilo<<<dim3(QKV3 / 32, DIM_ / 32), dim3(32, 8)>>>(Wqkv, wqh, wql, DIM_, QKV3);
    transpose_hilo<<<dim3(HDH / 32, HDH / 32), dim3(32, 8)>>>(Wout, woh, wol, HDH, HDH);

    // 2) QKV GEMM (mma.sync bf16 hi/lo): [8192,1536] @ [1536,4608]
    gemm_mma<<<dim3(QKV3 / 128, M_ / 128), 256, GEMM_SMEM>>>(
        xhi, xlo, wqh, wql, nullptr, qkv, QKV3, DIM_);

    // 3) RoPE + head transpose
    rope_kernel<<<3 * B_ * H_ * N_ * DH_ / 256, 256>>>(f1, f2, f3);

    // 4) Flash attention (fp32)
    flash_kernel<<<dim3(N_ / BM, B_ * H_), 256, FLASH_SMEM_BYTES>>>();

    // 5) ctx -> hi/lo, then output GEMM + bias
    cvt_hilo<<<(M_ * HDH / 4 + 255) / 256, 256>>>(ctx, chi, clo, M_ * HDH / 4);
    gemm_mma<<<dim3(HDH / 128, M_ / 128), 256, GEMM_SMEM>>>(
        chi, clo, woh, wol, bout, out, HDH, HDH);
}

// round 5
// speedup vs baseline: 3.1443x; 2.4537x over previous
#include <cuda_runtime.h>
#include <cuda_bf16.h>
#include <cstdint>

#define B_    4
#define N_    2048
#define DIM_  1536
#define H_    16
#define DH_   96
#define QKV3  4608      // 3*H*DH
#define HDH   1536      // H*DH
#define M_    (B_*N_)   // 8192
#define SCALE_ 0.10206207261596575f  // 96^-0.5

// ---------------- scratch (no allocations allowed) ----------------
__device__ float g_qkv[(size_t)M_ * QKV3];           // 151 MB
__device__ float g_ctx[(size_t)M_ * HDH];            // 50 MB

__device__ __nv_bfloat16 g_xhi[(size_t)M_ * DIM_];
__device__ __nv_bfloat16 g_xlo[(size_t)M_ * DIM_];
__device__ __nv_bfloat16 g_chi[(size_t)M_ * HDH];
__device__ __nv_bfloat16 g_clo[(size_t)M_ * HDH];
__device__ __nv_bfloat16 g_wqh[(size_t)QKV3 * DIM_]; // W^T [N,K]
__device__ __nv_bfloat16 g_wql[(size_t)QKV3 * DIM_];
__device__ __nv_bfloat16 g_woh[(size_t)HDH * HDH];
__device__ __nv_bfloat16 g_wol[(size_t)HDH * HDH];

// q/k/v hi-lo bf16, layout [b*H + h][n][d] (d contiguous); q pre-scaled
#define PER_T ((size_t)B_ * H_ * N_ * DH_)
__device__ __nv_bfloat16 g_qhi[PER_T];
__device__ __nv_bfloat16 g_qlo[PER_T];
__device__ __nv_bfloat16 g_khi[PER_T];
__device__ __nv_bfloat16 g_klo[PER_T];
__device__ __nv_bfloat16 g_vhi[PER_T];
__device__ __nv_bfloat16 g_vlo[PER_T];

// ================= helpers (sm_80+ only) ==========================
__device__ __forceinline__ uint32_t smem_u32(const void* p) {
    uint32_t a;
    asm("{ .reg .u64 t; cvta.to.shared.u64 t, %1; cvt.u32.u64 %0, t; }"
        : "=r"(a) : "l"(p));
    return a;
}
__device__ __forceinline__ uint32_t lds32(uint32_t a) {
    uint32_t v;
    asm volatile("ld.shared.b32 %0, [%1];" : "=r"(v) : "r"(a));
    return v;
}
#define CP_ASYNC16(saddr, gptr) \
    asm volatile("cp.async.cg.shared.global [%0], [%1], 16;" :: "r"(saddr), "l"(gptr))
#define CP_COMMIT() asm volatile("cp.async.commit_group;" ::: "memory")
#define CP_WAIT(n)  asm volatile("cp.async.wait_group %0;" :: "n"(n) : "memory")

#define LDMX4(r0,r1,r2,r3,addr) \
    asm volatile("ldmatrix.sync.aligned.m8n8.x4.shared.b16 {%0,%1,%2,%3}, [%4];" \
        : "=r"(r0),"=r"(r1),"=r"(r2),"=r"(r3) : "r"(addr))
#define LDMX4T(r0,r1,r2,r3,addr) \
    asm volatile("ldmatrix.sync.aligned.m8n8.x4.trans.shared.b16 {%0,%1,%2,%3}, [%4];" \
        : "=r"(r0),"=r"(r1),"=r"(r2),"=r"(r3) : "r"(addr))

__device__ __forceinline__ void mma_bf16(float* c, const uint32_t* a, const uint32_t* b) {
    asm volatile(
        "mma.sync.aligned.m16n8k16.row.col.f32.bf16.bf16.f32 "
        "{%0,%1,%2,%3}, {%4,%5,%6,%7}, {%8,%9}, {%0,%1,%2,%3};"
        : "+f"(c[0]), "+f"(c[1]), "+f"(c[2]), "+f"(c[3])
        : "r"(a[0]), "r"(a[1]), "r"(a[2]), "r"(a[3]), "r"(b[0]), "r"(b[1]));
}
__device__ __forceinline__ uint32_t pk_bf16x2(float a, float b) {
    __nv_bfloat162 t = __floats2bfloat162_rn(a, b);
    return *(uint32_t*)&t;
}

// ====== split-bf16 mma.sync GEMM (unchanged from R4) ==============
#define GS_STRIDE 80
#define GS_TILE   10240
#define GS_STAGE  40960
#define GEMM_SMEM (2 * GS_STAGE)

__global__ void __launch_bounds__(256, 1)
gemm_mma(const __nv_bfloat16* __restrict__ Ahi, const __nv_bfloat16* __restrict__ Alo,
         const __nv_bfloat16* __restrict__ Bhi, const __nv_bfloat16* __restrict__ Blo,
         const float* __restrict__ bias, float* __restrict__ C, int N, int K) {
    extern __shared__ char sm_[];
    const uint32_t sb = smem_u32(sm_);
    const int tid = threadIdx.x;
    const int wid = tid >> 5, lane = tid & 31;
    const int g = lane >> 2, tg = lane & 3;
    const int wm = wid & 3, wn = wid >> 2;
    const int brow = blockIdx.y * 128;
    const int bcol = blockIdx.x * 128;

    float acc[2][8][4];
#pragma unroll
    for (int mt = 0; mt < 2; mt++)
#pragma unroll
        for (int nt = 0; nt < 8; nt++)
#pragma unroll
            for (int i = 0; i < 4; i++) acc[mt][nt][i] = 0.f;

    const char* gsrc0 = (const char*)Ahi;
    const char* gsrc1 = (const char*)Alo;
    const char* gsrc2 = (const char*)Bhi;
    const char* gsrc3 = (const char*)Blo;
    const int nst = K / 32;

    auto load_stage = [&](int s) {
        const uint32_t base = sb + (uint32_t)(s & 1) * GS_STAGE;
        const int k0 = s * 32;
#pragma unroll
        for (int j = 0; j < 2; j++) {
            const int idx = tid * 2 + j;
            const int r = idx >> 2, c = idx & 3;
            const uint32_t so = (uint32_t)r * GS_STRIDE + (uint32_t)c * 16;
            const size_t goA = ((size_t)(brow + r) * K + k0 + c * 8) * 2;
            const size_t goB = ((size_t)(bcol + r) * K + k0 + c * 8) * 2;
            CP_ASYNC16(base + so,                gsrc0 + goA);
            CP_ASYNC16(base + GS_TILE + so,      gsrc1 + goA);
            CP_ASYNC16(base + 2 * GS_TILE + so,  gsrc2 + goB);
            CP_ASYNC16(base + 3 * GS_TILE + so,  gsrc3 + goB);
        }
    };

    load_stage(0); CP_COMMIT();

    for (int s = 0; s < nst; s++) {
        if (s + 1 < nst) { load_stage(s + 1); CP_COMMIT(); CP_WAIT(1); }
        else             { CP_WAIT(0); }
        __syncthreads();

        const uint32_t base = sb + (uint32_t)(s & 1) * GS_STAGE;
#pragma unroll
        for (int kk = 0; kk < 2; kk++) {
            const uint32_t colb = (uint32_t)(kk * 16 + tg * 2) * 2;
            uint32_t ah[2][4], al[2][4], bh[8][2], bl[8][2];
#pragma unroll
            for (int mt = 0; mt < 2; mt++) {
                const uint32_t r0 = (uint32_t)(wm * 32 + mt * 16 + g);
                const uint32_t o0 = base + r0 * GS_STRIDE + colb;
                const uint32_t o1 = base + (r0 + 8) * GS_STRIDE + colb;
                ah[mt][0] = lds32(o0);
                ah[mt][1] = lds32(o1);
                ah[mt][2] = lds32(o0 + 16);
                ah[mt][3] = lds32(o1 + 16);
                al[mt][0] = lds32(o0 + GS_TILE);
                al[mt][1] = lds32(o1 + GS_TILE);
                al[mt][2] = lds32(o0 + GS_TILE + 16);
                al[mt][3] = lds32(o1 + GS_TILE + 16);
            }
#pragma unroll
            for (int nt = 0; nt < 8; nt++) {
                const uint32_t n0 = (uint32_t)(wn * 64 + nt * 8 + g);
                const uint32_t ob = base + 2 * GS_TILE + n0 * GS_STRIDE + colb;
                bh[nt][0] = lds32(ob);
                bh[nt][1] = lds32(ob + 16);
                bl[nt][0] = lds32(ob + GS_TILE);
                bl[nt][1] = lds32(ob + GS_TILE + 16);
            }
#pragma unroll
            for (int mt = 0; mt < 2; mt++)
#pragma unroll
                for (int nt = 0; nt < 8; nt++) {
                    mma_bf16(acc[mt][nt], ah[mt], bh[nt]);
                    mma_bf16(acc[mt][nt], ah[mt], bl[nt]);
                    mma_bf16(acc[mt][nt], al[mt], bh[nt]);
                }
        }
        __syncthreads();
    }

#pragma unroll
    for (int mt = 0; mt < 2; mt++) {
        const int r0 = brow + wm * 32 + mt * 16 + g;
#pragma unroll
        for (int nt = 0; nt < 8; nt++) {
            const int c = bcol + wn * 64 + nt * 8 + tg * 2;
            float2 v0 = make_float2(acc[mt][nt][0], acc[mt][nt][1]);
            float2 v1 = make_float2(acc[mt][nt][2], acc[mt][nt][3]);
            if (bias) {
                const float b0 = bias[c], b1 = bias[c + 1];
                v0.x += b0; v0.y += b1; v1.x += b0; v1.y += b1;
            }
            *(float2*)(C + (size_t)r0 * N + c)       = v0;
            *(float2*)(C + (size_t)(r0 + 8) * N + c) = v1;
        }
    }
}

// ---------------- hi/lo conversion kernels ------------------------
__global__ void cvt_hilo(const float* __restrict__ src,
                         __nv_bfloat16* __restrict__ hi,
                         __nv_bfloat16* __restrict__ lo, int n4) {
    const int i = blockIdx.x * blockDim.x + threadIdx.x;
    if (i >= n4) return;
    const float4 v = ((const float4*)src)[i];
    float h0 = __bfloat162float(__float2bfloat16(v.x));
    float h1 = __bfloat162float(__float2bfloat16(v.y));
    float h2 = __bfloat162float(__float2bfloat16(v.z));
    float h3 = __bfloat162float(__float2bfloat16(v.w));
    ((__nv_bfloat162*)hi)[i * 2]     = __floats2bfloat162_rn(v.x, v.y);
    ((__nv_bfloat162*)hi)[i * 2 + 1] = __floats2bfloat162_rn(v.z, v.w);
    ((__nv_bfloat162*)lo)[i * 2]     = __floats2bfloat162_rn(v.x - h0, v.y - h1);
    ((__nv_bfloat162*)lo)[i * 2 + 1] = __floats2bfloat162_rn(v.z - h2, v.w - h3);
}

__global__ void transpose_hilo(const float* __restrict__ W,
                               __nv_bfloat16* __restrict__ hi,
                               __nv_bfloat16* __restrict__ lo, int K, int N) {
    __shared__ float t[32][33];
    const int n0 = blockIdx.x * 32, k0 = blockIdx.y * 32;
    const int tx = threadIdx.x;
    for (int y = threadIdx.y; y < 32; y += 8)
        t[y][tx] = W[(size_t)(k0 + y) * N + n0 + tx];
    __syncthreads();
    for (int y = threadIdx.y; y < 32; y += 8) {
        const float v = t[tx][y];
        const __nv_bfloat16 h = __float2bfloat16(v);
        const size_t o = (size_t)(n0 + y) * K + k0 + tx;
        hi[o] = h;
        lo[o] = __float2bfloat16(v - __bfloat162float(h));
    }
}

// ------- RoPE + head transpose, emit hi/lo bf16 (q pre-scaled) ----
__global__ void rope_kernel(const float* __restrict__ f1,
                            const float* __restrict__ f2,
                            const float* __restrict__ f3) {
    const int per = B_ * H_ * N_ * DH_;
    int idx = blockIdx.x * blockDim.x + threadIdx.x;
    if (idx >= 3 * per) return;
    const int which = idx / per;
    int r = idx - which * per;
    const int d = r % DH_;  r /= DH_;
    const int n = r % N_;   r /= N_;
    const int h = r % H_;
    const int b = r / H_;

    const size_t src_row = (size_t)(b * N_ + n) * QKV3;
    const int base = which * HDH + h * DH_;
    const float t = g_qkv[src_row + base + d];

    float outv;
    if (which == 2) {
        outv = t;
    } else {
        const int c = d >> 5;
        const int j = d & 31;
        const float* f = (c == 0) ? f1 : ((c == 1) ? f2 : f3);
        const float fr = f[n * 32 + j];
        float rot;
        if (j < 16) rot = -g_qkv[src_row + base + c * 32 + j + 16];
        else        rot =  g_qkv[src_row + base + c * 32 + j - 16];
        outv = t * __cosf(fr) + rot * __sinf(fr);
        if (which == 0) outv *= SCALE_;   // fold attention scale into q
    }
    __nv_bfloat16* hi = (which == 0) ? g_qhi : ((which == 1) ? g_khi : g_vhi);
    __nv_bfloat16* lo = (which == 0) ? g_qlo : ((which == 1) ? g_klo : g_vlo);
    const size_t o = (size_t)((b * H_ + h) * N_ + n) * DH_ + d;
    const __nv_bfloat16 hv = __float2bfloat16(outv);
    hi[o] = hv;
    lo[o] = __float2bfloat16(outv - __bfloat162float(hv));
}

// ---------------- Flash attention (mma.sync bf16 hi/lo) -----------
// CTA: 128 Q rows, 8 warps x 16 rows. KV tile 64, double-buffered cp.async.
// smem tiles [64 rows][208 B] (96 bf16 + pad): Khi,Klo,Vhi,Vlo per stage.
#define FBM    128
#define FBN    64
#define FSTRIDE 208
#define FTILE  (64 * FSTRIDE)      // 13312
#define FSTAGE (4 * FTILE)         // 53248
#define FLASH_SMEM (2 * FSTAGE)    // 106496

__global__ void __launch_bounds__(256, 1) flash_mma() {
    extern __shared__ char sm_[];
    const uint32_t sb = smem_u32(sm_);
    const int tid = threadIdx.x;
    const int wid = tid >> 5, lane = tid & 31;
    const int g = lane >> 2, tg = lane & 3;
    const int bh = blockIdx.y;
    const int b  = bh >> 4, h = bh & 15;
    const int m0 = blockIdx.x * FBM;

    const size_t tbase = (size_t)bh * N_ * DH_;

    // ---- Q fragments (held in regs for the whole kernel) ----
    const int qrow = m0 + wid * 16 + g;
    const char* qh = (const char*)(g_qhi + tbase + (size_t)qrow * DH_);
    const char* ql = (const char*)(g_qlo + tbase + (size_t)qrow * DH_);
    uint32_t qa_h[6][4], qa_l[6][4];
#pragma unroll
    for (int j = 0; j < 6; j++) {
        const int c0 = (j * 16 + tg * 2) * 2;
        qa_h[j][0] = *(const uint32_t*)(qh + c0);
        qa_h[j][1] = *(const uint32_t*)(qh + 8 * DH_ * 2 + c0);
        qa_h[j][2] = *(const uint32_t*)(qh + c0 + 16);
        qa_h[j][3] = *(const uint32_t*)(qh + 8 * DH_ * 2 + c0 + 16);
        qa_l[j][0] = *(const uint32_t*)(ql + c0);
        qa_l[j][1] = *(const uint32_t*)(ql + 8 * DH_ * 2 + c0);
        qa_l[j][2] = *(const uint32_t*)(ql + c0 + 16);
        qa_l[j][3] = *(const uint32_t*)(ql + 8 * DH_ * 2 + c0 + 16);
    }

    float oacc[12][4];
#pragma unroll
    for (int ot = 0; ot < 12; ot++)
#pragma unroll
        for (int i = 0; i < 4; i++) oacc[ot][i] = 0.f;
    float mrow0 = -1e30f, mrow1 = -1e30f, lrow0 = 0.f, lrow1 = 0.f;

    const char* srcs[4] = {
        (const char*)(g_khi + tbase), (const char*)(g_klo + tbase),
        (const char*)(g_vhi + tbase), (const char*)(g_vlo + tbase)};

    auto load_stage = [&](int s) {
        const uint32_t base = sb + (uint32_t)(s & 1) * FSTAGE;
        const int n0 = s * FBN;
#pragma unroll
        for (int c = 0; c < 3; c++) {
            const int chunk = tid + c * 256;        // 0..767
            const int r = chunk / 12, col = chunk % 12;
            const uint32_t so = (uint32_t)r * FSTRIDE + (uint32_t)col * 16;
            const size_t go = ((size_t)(n0 + r) * DH_ + col * 8) * 2;
#pragma unroll
            for (int t = 0; t < 4; t++)
                CP_ASYNC16(base + t * FTILE + so, srcs[t] + go);
        }
    };

    load_stage(0); CP_COMMIT();

    const int nkv = N_ / FBN;   // 32
    for (int s = 0; s < nkv; s++) {
        if (s + 1 < nkv) { load_stage(s + 1); CP_COMMIT(); CP_WAIT(1); }
        else             { CP_WAIT(0); }
        __syncthreads();

        const uint32_t kb = sb + (uint32_t)(s & 1) * FSTAGE;   // Khi
        const uint32_t vb = kb + 2 * FTILE;                    // Vhi

        // ---- S = Q K^T (scaled; q pre-scaled) ----
        float sacc[8][4];
#pragma unroll
        for (int nt = 0; nt < 8; nt++)
#pragma unroll
            for (int i = 0; i < 4; i++) sacc[nt][i] = 0.f;

#pragma unroll
        for (int j = 0; j < 6; j++) {
            uint32_t bfh[8][2], bfl[8][2];
#pragma unroll
            for (int np = 0; np < 4; np++) {
                const int sel = lane >> 3;
                const uint32_t row = (uint32_t)(np * 16 + ((sel & 2) ? 8 : 0) + (lane & 7));
                const uint32_t col = (uint32_t)(j * 16 + ((sel & 1) ? 8 : 0));
                const uint32_t ad = kb + row * FSTRIDE + col * 2;
                LDMX4(bfh[2*np][0], bfh[2*np][1], bfh[2*np+1][0], bfh[2*np+1][1], ad);
                LDMX4(bfl[2*np][0], bfl[2*np][1], bfl[2*np+1][0], bfl[2*np+1][1], ad + FTILE);
            }
#pragma unroll
            for (int nt = 0; nt < 8; nt++) {
                mma_bf16(sacc[nt], qa_h[j], bfh[nt]);
                mma_bf16(sacc[nt], qa_h[j], bfl[nt]);
                mma_bf16(sacc[nt], qa_l[j], bfh[nt]);
            }
        }

        // ---- online softmax (rows g and g+8; quad-level reductions) ----
        float mx0 = -1e30f, mx1 = -1e30f;
#pragma unroll
        for (int nt = 0; nt < 8; nt++) {
            mx0 = fmaxf(mx0, fmaxf(sacc[nt][0], sacc[nt][1]));
            mx1 = fmaxf(mx1, fmaxf(sacc[nt][2], sacc[nt][3]));
        }
        mx0 = fmaxf(mx0, __shfl_xor_sync(0xffffffffu, mx0, 1));
        mx0 = fmaxf(mx0, __shfl_xor_sync(0xffffffffu, mx0, 2));
        mx1 = fmaxf(mx1, __shfl_xor_sync(0xffffffffu, mx1, 1));
        mx1 = fmaxf(mx1, __shfl_xor_sync(0xffffffffu, mx1, 2));

        const float mn0 = fmaxf(mrow0, mx0), mn1 = fmaxf(mrow1, mx1);
        const float corr0 = __expf(mrow0 - mn0), corr1 = __expf(mrow1 - mn1);
        mrow0 = mn0; mrow1 = mn1;

        float sum0 = 0.f, sum1 = 0.f;
#pragma unroll
        for (int nt = 0; nt < 8; nt++) {
            sacc[nt][0] = __expf(sacc[nt][0] - mn0);
            sacc[nt][1] = __expf(sacc[nt][1] - mn0);
            sacc[nt][2] = __expf(sacc[nt][2] - mn1);
            sacc[nt][3] = __expf(sacc[nt][3] - mn1);
            sum0 += sacc[nt][0] + sacc[nt][1];
            sum1 += sacc[nt][2] + sacc[nt][3];
        }
        lrow0 = lrow0 * corr0 + sum0;
        lrow1 = lrow1 * corr1 + sum1;
#pragma unroll
        for (int ot = 0; ot < 12; ot++) {
            oacc[ot][0] *= corr0; oacc[ot][1] *= corr0;
            oacc[ot][2] *= corr1; oacc[ot][3] *= corr1;
        }

        // ---- O += P V ----
#pragma unroll
        for (int jj = 0; jj < 4; jj++) {
            uint32_t pa_h[4], pa_l[4];
            {
                const float p00 = sacc[2*jj][0],   p01 = sacc[2*jj][1];
                const float p10 = sacc[2*jj][2],   p11 = sacc[2*jj][3];
                const float p20 = sacc[2*jj+1][0], p21 = sacc[2*jj+1][1];
                const float p30 = sacc[2*jj+1][2], p31 = sacc[2*jj+1][3];
                pa_h[0] = pk_bf16x2(p00, p01);
                pa_h[1] = pk_bf16x2(p10, p11);
                pa_h[2] = pk_bf16x2(p20, p21);
                pa_h[3] = pk_bf16x2(p30, p31);
                pa_l[0] = pk_bf16x2(p00 - __bfloat162float(__float2bfloat16(p00)),
                                    p01 - __bfloat162float(__float2bfloat16(p01)));
                pa_l[1] = pk_bf16x2(p10 - __bfloat162float(__float2bfloat16(p10)),
                                    p11 - __bfloat162float(__float2bfloat16(p11)));
                pa_l[2] = pk_bf16x2(p20 - __bfloat162float(__float2bfloat16(p20)),
                                    p21 - __bfloat162float(__float2bfloat16(p21)));
                pa_l[3] = pk_bf16x2(p30 - __bfloat162float(__float2bfloat16(p30)),
                                    p31 - __bfloat162float(__float2bfloat16(p31)));
            }
#pragma unroll
            for (int np = 0; np < 6; np++) {
                uint32_t vfh[2][2], vfl[2][2];
                const int sel = lane >> 3;
                const uint32_t row = (uint32_t)(jj * 16 + ((sel & 1) ? 8 : 0) + (lane & 7));
                const uint32_t col = (uint32_t)(np * 16 + ((sel & 2) ? 8 : 0));
                const uint32_t ad = vb + row * FSTRIDE + col * 2;
                LDMX4T(vfh[0][0], vfh[0][1], vfh[1][0], vfh[1][1], ad);
                LDMX4T(vfl[0][0], vfl[0][1], vfl[1][0], vfl[1][1], ad + FTILE);
                mma_bf16(oacc[2*np],   pa_h, vfh[0]);
                mma_bf16(oacc[2*np],   pa_h, vfl[0]);
                mma_bf16(oacc[2*np],   pa_l, vfh[0]);
                mma_bf16(oacc[2*np+1], pa_h, vfh[1]);
                mma_bf16(oacc[2*np+1], pa_h, vfl[1]);
                mma_bf16(oacc[2*np+1], pa_l, vfh[1]);
            }
        }
        __syncthreads();
    }

    // ---- finalize: 1/l, write ctx[b][n][h*96+d] ----
    lrow0 += __shfl_xor_sync(0xffffffffu, lrow0, 1);
    lrow0 += __shfl_xor_sync(0xffffffffu, lrow0, 2);
    lrow1 += __shfl_xor_sync(0xffffffffu, lrow1, 1);
    lrow1 += __shfl_xor_sync(0xffffffffu, lrow1, 2);
    const float inv0 = 1.f / lrow0, inv1 = 1.f / lrow1;

    const int nrow = m0 + wid * 16 + g;
    float* o0 = g_ctx + (size_t)(b * N_ + nrow) * HDH + h * DH_;
    float* o1 = g_ctx + (size_t)(b * N_ + nrow + 8) * HDH + h * DH_;
#pragma unroll
    for (int ot = 0; ot < 12; ot++) {
        const int d0 = ot * 8 + tg * 2;
        *(float2*)(o0 + d0) = make_float2(oacc[ot][0] * inv0, oacc[ot][1] * inv0);
        *(float2*)(o1 + d0) = make_float2(oacc[ot][2] * inv1, oacc[ot][3] * inv1);
    }
}

// ------------------------------------------------------------------
extern "C" void kernel_launch(void* const* d_in, const int* in_sizes, int n_in,
                              void* d_out, int out_size) {
    const float* x    = (const float*)d_in[0];
    const float* f1   = (const float*)d_in[1];
    const float* f2   = (const float*)d_in[2];
    const float* f3   = (const float*)d_in[3];
    const float* Wqkv = (const float*)d_in[4];
    const float* Wout = (const float*)d_in[5];
    const float* bout = (const float*)d_in[6];
    float* out = (float*)d_out;

    float *qkv, *ctx;
    __nv_bfloat16 *xhi, *xlo, *chi, *clo, *wqh, *wql, *woh, *wol;
    cudaGetSymbolAddress((void**)&qkv, g_qkv);
    cudaGetSymbolAddress((void**)&ctx, g_ctx);
    cudaGetSymbolAddress((void**)&xhi, g_xhi);
    cudaGetSymbolAddress((void**)&xlo, g_xlo);
    cudaGetSymbolAddress((void**)&chi, g_chi);
    cudaGetSymbolAddress((void**)&clo, g_clo);
    cudaGetSymbolAddress((void**)&wqh, g_wqh);
    cudaGetSymbolAddress((void**)&wql, g_wql);
    cudaGetSymbolAddress((void**)&woh, g_woh);
    cudaGetSymbolAddress((void**)&wol, g_wol);

    cudaFuncSetAttribute(gemm_mma, cudaFuncAttributeMaxDynamicSharedMemorySize, GEMM_SMEM);
    cudaFuncSetAttribute(flash_mma, cudaFuncAttributeMaxDynamicSharedMemorySize, FLASH_SMEM);

    // 1) x -> hi/lo; weights -> transposed hi/lo
    cvt_hilo<<<(M_ * DIM_ / 4 + 255) / 256, 256>>>(x, xhi, xlo, M_ * DIM_ / 4);
    transpose_hilo<<<dim3(QKV3 / 32, DIM_ / 32), dim3(32, 8)>>>(Wqkv, wqh, wql, DIM_, QKV3);
    transpose_hilo<<<dim3(HDH / 32, HDH / 32), dim3(32, 8)>>>(Wout, woh, wol, HDH, HDH);

    // 2) QKV GEMM
    gemm_mma<<<dim3(QKV3 / 128, M_ / 128), 256, GEMM_SMEM>>>(
        xhi, xlo, wqh, wql, nullptr, qkv, QKV3, DIM_);

    // 3) RoPE -> q/k/v hi/lo bf16 (q pre-scaled)
    rope_kernel<<<3 * B_ * H_ * N_ * DH_ / 256, 256>>>(f1, f2, f3);

    // 4) Flash attention on tensor cores
    flash_mma<<<dim3(N_ / FBM, B_ * H_), 256, FLASH_SMEM>>>();

    // 5) ctx -> hi/lo, output GEMM + bias
    cvt_hilo<<<(M_ * HDH / 4 + 255) / 256, 256>>>(ctx, chi, clo, M_ * HDH / 4);
    gemm_mma<<<dim3(HDH / 128, M_ / 128), 256, GEMM_SMEM>>>(
        chi, clo, woh, wol, bout, out, HDH, HDH);
}

// round 6
// speedup vs baseline: 4.6368x; 1.4747x over previous
#include <cuda_runtime.h>
#include <cuda_fp16.h>
#include <cstdint>

#define B_    4
#define N_    2048
#define DIM_  1536
#define H_    16
#define DH_   96
#define QKV3  4608      // 3*H*DH
#define HDH   1536      // H*DH
#define M_    (B_*N_)   // 8192
#define SCALE_ 0.10206207261596575f  // 96^-0.5

// ---------------- scratch (no allocations allowed) ----------------
__device__ float g_qkv[(size_t)M_ * QKV3];           // 151 MB
__device__ float g_ctx[(size_t)M_ * HDH];            // 50 MB

__device__ __half g_xhi[(size_t)M_ * DIM_];
__device__ __half g_xlo[(size_t)M_ * DIM_];
__device__ __half g_chi[(size_t)M_ * HDH];
__device__ __half g_clo[(size_t)M_ * HDH];
__device__ __half g_wqt[(size_t)QKV3 * DIM_];        // W^T [N,K] single fp16
__device__ __half g_wot[(size_t)HDH * HDH];

// q hi/lo; k, v single fp16. layout [b*H + h][n][d]; q pre-scaled
#define PER_T ((size_t)B_ * H_ * N_ * DH_)
__device__ __half g_qh[PER_T];
__device__ __half g_ql[PER_T];
__device__ __half g_kk[PER_T];
__device__ __half g_vv[PER_T];

// ================= helpers (sm_80+ only) ==========================
__device__ __forceinline__ uint32_t smem_u32(const void* p) {
    uint32_t a;
    asm("{ .reg .u64 t; cvta.to.shared.u64 t, %1; cvt.u32.u64 %0, t; }"
        : "=r"(a) : "l"(p));
    return a;
}
__device__ __forceinline__ uint32_t lds32(uint32_t a) {
    uint32_t v;
    asm volatile("ld.shared.b32 %0, [%1];" : "=r"(v) : "r"(a));
    return v;
}
#define CP_ASYNC16(saddr, gptr) \
    asm volatile("cp.async.cg.shared.global [%0], [%1], 16;" :: "r"(saddr), "l"(gptr))
#define CP_COMMIT() asm volatile("cp.async.commit_group;" ::: "memory")
#define CP_WAIT(n)  asm volatile("cp.async.wait_group %0;" :: "n"(n) : "memory")

#define LDMX4(r0,r1,r2,r3,addr) \
    asm volatile("ldmatrix.sync.aligned.m8n8.x4.shared.b16 {%0,%1,%2,%3}, [%4];" \
        : "=r"(r0),"=r"(r1),"=r"(r2),"=r"(r3) : "r"(addr))
#define LDMX4T(r0,r1,r2,r3,addr) \
    asm volatile("ldmatrix.sync.aligned.m8n8.x4.trans.shared.b16 {%0,%1,%2,%3}, [%4];" \
        : "=r"(r0),"=r"(r1),"=r"(r2),"=r"(r3) : "r"(addr))

__device__ __forceinline__ void mma_f16(float* c, const uint32_t* a, const uint32_t* b) {
    asm volatile(
        "mma.sync.aligned.m16n8k16.row.col.f32.f16.f16.f32 "
        "{%0,%1,%2,%3}, {%4,%5,%6,%7}, {%8,%9}, {%0,%1,%2,%3};"
        : "+f"(c[0]), "+f"(c[1]), "+f"(c[2]), "+f"(c[3])
        : "r"(a[0]), "r"(a[1]), "r"(a[2]), "r"(a[3]), "r"(b[0]), "r"(b[1]));
}
__device__ __forceinline__ uint32_t pk_h2(float a, float b) {
    __half2 t = __floats2half2_rn(a, b);
    return *(uint32_t*)&t;
}

// ====== 2-term fp16 mma.sync GEMM: C = (Ah+Al) @ Wt^T (+bias) =====
// Ah/Al [M,K] fp16 row-major; Wt [N,K] fp16 row-major. 3 smem tiles/stage.
#define GS_STRIDE 80            // 32 fp16 = 64 B data + 16 B pad (bank-clean)
#define GS_TILE   10240         // 128 rows * 80 B
#define GS_STAGE  30720         // Ah, Al, W tiles
#define GEMM_SMEM (2 * GS_STAGE)

__global__ void __launch_bounds__(256, 1)
gemm_mma(const __half* __restrict__ Ahi, const __half* __restrict__ Alo,
         const __half* __restrict__ Wt,
         const float* __restrict__ bias, float* __restrict__ C, int N, int K) {
    extern __shared__ char sm_[];
    const uint32_t sb = smem_u32(sm_);
    const int tid = threadIdx.x;
    const int wid = tid >> 5, lane = tid & 31;
    const int g = lane >> 2, tg = lane & 3;
    const int wm = wid & 3, wn = wid >> 2;
    const int brow = blockIdx.y * 128;
    const int bcol = blockIdx.x * 128;

    float acc[2][8][4];
#pragma unroll
    for (int mt = 0; mt < 2; mt++)
#pragma unroll
        for (int nt = 0; nt < 8; nt++)
#pragma unroll
            for (int i = 0; i < 4; i++) acc[mt][nt][i] = 0.f;

    const int nst = K / 32;

    // 3 tiles x 512 chunks(16B) = 1536; 6 per thread
    auto load_stage = [&](int s) {
        const uint32_t base = sb + (uint32_t)(s & 1) * GS_STAGE;
        const int k0 = s * 32;
#pragma unroll
        for (int i = 0; i < 6; i++) {
            const int idx = tid + i * 256;
            const int tile = idx >> 9;           // 0..2
            const int w = idx & 511;
            const int r = w >> 2, c = w & 3;
            const uint32_t so = base + (uint32_t)tile * GS_TILE +
                                (uint32_t)r * GS_STRIDE + (uint32_t)c * 16;
            const char* gp;
            if (tile == 0)      gp = (const char*)Ahi + ((size_t)(brow + r) * K + k0 + c * 8) * 2;
            else if (tile == 1) gp = (const char*)Alo + ((size_t)(brow + r) * K + k0 + c * 8) * 2;
            else                gp = (const char*)Wt  + ((size_t)(bcol + r) * K + k0 + c * 8) * 2;
            CP_ASYNC16(so, gp);
        }
    };

    load_stage(0); CP_COMMIT();

    for (int s = 0; s < nst; s++) {
        if (s + 1 < nst) { load_stage(s + 1); CP_COMMIT(); CP_WAIT(1); }
        else             { CP_WAIT(0); }
        __syncthreads();

        const uint32_t base = sb + (uint32_t)(s & 1) * GS_STAGE;
#pragma unroll
        for (int kk = 0; kk < 2; kk++) {
            const uint32_t colb = (uint32_t)(kk * 16 + tg * 2) * 2;
            uint32_t ah[2][4], al[2][4], bw[8][2];
#pragma unroll
            for (int mt = 0; mt < 2; mt++) {
                const uint32_t r0 = (uint32_t)(wm * 32 + mt * 16 + g);
                const uint32_t o0 = base + r0 * GS_STRIDE + colb;
                const uint32_t o1 = base + (r0 + 8) * GS_STRIDE + colb;
                ah[mt][0] = lds32(o0);
                ah[mt][1] = lds32(o1);
                ah[mt][2] = lds32(o0 + 16);
                ah[mt][3] = lds32(o1 + 16);
                al[mt][0] = lds32(o0 + GS_TILE);
                al[mt][1] = lds32(o1 + GS_TILE);
                al[mt][2] = lds32(o0 + GS_TILE + 16);
                al[mt][3] = lds32(o1 + GS_TILE + 16);
            }
#pragma unroll
            for (int nt = 0; nt < 8; nt++) {
                const uint32_t n0 = (uint32_t)(wn * 64 + nt * 8 + g);
                const uint32_t ob = base + 2 * GS_TILE + n0 * GS_STRIDE + colb;
                bw[nt][0] = lds32(ob);
                bw[nt][1] = lds32(ob + 16);
            }
#pragma unroll
            for (int mt = 0; mt < 2; mt++)
#pragma unroll
                for (int nt = 0; nt < 8; nt++) {
                    mma_f16(acc[mt][nt], ah[mt], bw[nt]);
                    mma_f16(acc[mt][nt], al[mt], bw[nt]);
                }
        }
        __syncthreads();
    }

#pragma unroll
    for (int mt = 0; mt < 2; mt++) {
        const int r0 = brow + wm * 32 + mt * 16 + g;
#pragma unroll
        for (int nt = 0; nt < 8; nt++) {
            const int c = bcol + wn * 64 + nt * 8 + tg * 2;
            float2 v0 = make_float2(acc[mt][nt][0], acc[mt][nt][1]);
            float2 v1 = make_float2(acc[mt][nt][2], acc[mt][nt][3]);
            if (bias) {
                const float b0 = bias[c], b1 = bias[c + 1];
                v0.x += b0; v0.y += b1; v1.x += b0; v1.y += b1;
            }
            *(float2*)(C + (size_t)r0 * N + c)       = v0;
            *(float2*)(C + (size_t)(r0 + 8) * N + c) = v1;
        }
    }
}

// ---------------- fp32 -> fp16 hi/lo --------------------------------
__global__ void cvt_hilo(const float* __restrict__ src,
                         __half* __restrict__ hi, __half* __restrict__ lo, int n4) {
    const int i = blockIdx.x * blockDim.x + threadIdx.x;
    if (i >= n4) return;
    const float4 v = ((const float4*)src)[i];
    const __half h0 = __float2half(v.x), h1 = __float2half(v.y);
    const __half h2 = __float2half(v.z), h3 = __float2half(v.w);
    ((__half2*)hi)[i * 2]     = __halves2half2(h0, h1);
    ((__half2*)hi)[i * 2 + 1] = __halves2half2(h2, h3);
    ((__half2*)lo)[i * 2]     = __floats2half2_rn(v.x - __half2float(h0), v.y - __half2float(h1));
    ((__half2*)lo)[i * 2 + 1] = __floats2half2_rn(v.z - __half2float(h2), v.w - __half2float(h3));
}

// W [K,N] -> W^T [N,K] single fp16
__global__ void transpose_f16(const float* __restrict__ W,
                              __half* __restrict__ Wt, int K, int N) {
    __shared__ float t[32][33];
    const int n0 = blockIdx.x * 32, k0 = blockIdx.y * 32;
    const int tx = threadIdx.x;
    for (int y = threadIdx.y; y < 32; y += 8)
        t[y][tx] = W[(size_t)(k0 + y) * N + n0 + tx];
    __syncthreads();
    for (int y = threadIdx.y; y < 32; y += 8)
        Wt[(size_t)(n0 + y) * K + k0 + tx] = __float2half(t[tx][y]);
}

// ------- RoPE + head transpose: q -> hi/lo (pre-scaled), k/v fp16 -
__global__ void rope_kernel(const float* __restrict__ f1,
                            const float* __restrict__ f2,
                            const float* __restrict__ f3) {
    const int per = B_ * H_ * N_ * DH_;
    int idx = blockIdx.x * blockDim.x + threadIdx.x;
    if (idx >= 3 * per) return;
    const int which = idx / per;
    int r = idx - which * per;
    const int d = r % DH_;  r /= DH_;
    const int n = r % N_;   r /= N_;
    const int h = r % H_;
    const int b = r / H_;

    const size_t src_row = (size_t)(b * N_ + n) * QKV3;
    const int base = which * HDH + h * DH_;
    const float t = g_qkv[src_row + base + d];

    float outv;
    if (which == 2) {
        outv = t;
    } else {
        const int c = d >> 5;
        const int j = d & 31;
        const float* f = (c == 0) ? f1 : ((c == 1) ? f2 : f3);
        const float fr = f[n * 32 + j];
        float rot;
        if (j < 16) rot = -g_qkv[src_row + base + c * 32 + j + 16];
        else        rot =  g_qkv[src_row + base + c * 32 + j - 16];
        outv = t * __cosf(fr) + rot * __sinf(fr);
        if (which == 0) outv *= SCALE_;
    }
    const size_t o = (size_t)((b * H_ + h) * N_ + n) * DH_ + d;
    if (which == 0) {
        const __half hv = __float2half(outv);
        g_qh[o] = hv;
        g_ql[o] = __float2half(outv - __half2float(hv));
    } else if (which == 1) {
        g_kk[o] = __float2half(outv);
    } else {
        g_vv[o] = __float2half(outv);
    }
}

// ---------------- Flash attention (fp16 2-term mma.sync) ----------
// CTA 128 Q rows, 8 warps x 16. KV tile 64, double-buffered.
// smem per stage: K(64x208) + V(64x208). Q hi/lo in regs; P split hi/lo.
#define FBM    128
#define FBN    64
#define FSTRIDE 208
#define FTILE  (64 * FSTRIDE)      // 13312
#define FSTAGE (2 * FTILE)         // 26624
#define FLASH_SMEM (2 * FSTAGE)    // 53248

__global__ void __launch_bounds__(256, 1) flash_mma() {
    extern __shared__ char sm_[];
    const uint32_t sb = smem_u32(sm_);
    const int tid = threadIdx.x;
    const int wid = tid >> 5, lane = tid & 31;
    const int g = lane >> 2, tg = lane & 3;
    const int bh = blockIdx.y;
    const int b  = bh >> 4, h = bh & 15;
    const int m0 = blockIdx.x * FBM;

    const size_t tbase = (size_t)bh * N_ * DH_;

    // ---- Q fragments (persistent) ----
    const int qrow = m0 + wid * 16 + g;
    const char* qh = (const char*)(g_qh + tbase + (size_t)qrow * DH_);
    const char* ql = (const char*)(g_ql + tbase + (size_t)qrow * DH_);
    uint32_t qa_h[6][4], qa_l[6][4];
#pragma unroll
    for (int j = 0; j < 6; j++) {
        const int c0 = (j * 16 + tg * 2) * 2;
        qa_h[j][0] = *(const uint32_t*)(qh + c0);
        qa_h[j][1] = *(const uint32_t*)(qh + 8 * DH_ * 2 + c0);
        qa_h[j][2] = *(const uint32_t*)(qh + c0 + 16);
        qa_h[j][3] = *(const uint32_t*)(qh + 8 * DH_ * 2 + c0 + 16);
        qa_l[j][0] = *(const uint32_t*)(ql + c0);
        qa_l[j][1] = *(const uint32_t*)(ql + 8 * DH_ * 2 + c0);
        qa_l[j][2] = *(const uint32_t*)(ql + c0 + 16);
        qa_l[j][3] = *(const uint32_t*)(ql + 8 * DH_ * 2 + c0 + 16);
    }

    float oacc[12][4];
#pragma unroll
    for (int ot = 0; ot < 12; ot++)
#pragma unroll
        for (int i = 0; i < 4; i++) oacc[ot][i] = 0.f;
    float mrow0 = -1e30f, mrow1 = -1e30f, lrow0 = 0.f, lrow1 = 0.f;

    const char* srcK = (const char*)(g_kk + tbase);
    const char* srcV = (const char*)(g_vv + tbase);

    // 2 tiles x 768 chunks = 1536; 6 per thread
    auto load_stage = [&](int s) {
        const uint32_t base = sb + (uint32_t)(s & 1) * FSTAGE;
        const int n0 = s * FBN;
#pragma unroll
        for (int i = 0; i < 6; i++) {
            const int idx = tid + i * 256;
            const int tile = idx / 768;
            const int w = idx % 768;
            const int r = w / 12, c = w % 12;
            const uint32_t so = base + (uint32_t)tile * FTILE +
                                (uint32_t)r * FSTRIDE + (uint32_t)c * 16;
            const size_t go = ((size_t)(n0 + r) * DH_ + c * 8) * 2;
            CP_ASYNC16(so, (tile == 0 ? srcK : srcV) + go);
        }
    };

    load_stage(0); CP_COMMIT();

    const int nkv = N_ / FBN;   // 32
    for (int s = 0; s < nkv; s++) {
        if (s + 1 < nkv) { load_stage(s + 1); CP_COMMIT(); CP_WAIT(1); }
        else             { CP_WAIT(0); }
        __syncthreads();

        const uint32_t kb = sb + (uint32_t)(s & 1) * FSTAGE;   // K
        const uint32_t vb = kb + FTILE;                        // V

        // ---- S = Q K^T ----
        float sacc[8][4];
#pragma unroll
        for (int nt = 0; nt < 8; nt++)
#pragma unroll
            for (int i = 0; i < 4; i++) sacc[nt][i] = 0.f;

#pragma unroll
        for (int j = 0; j < 6; j++) {
            uint32_t bf[8][2];
#pragma unroll
            for (int np = 0; np < 4; np++) {
                const int sel = lane >> 3;
                const uint32_t row = (uint32_t)(np * 16 + ((sel & 2) ? 8 : 0) + (lane & 7));
                const uint32_t col = (uint32_t)(j * 16 + ((sel & 1) ? 8 : 0));
                const uint32_t ad = kb + row * FSTRIDE + col * 2;
                LDMX4(bf[2*np][0], bf[2*np][1], bf[2*np+1][0], bf[2*np+1][1], ad);
            }
#pragma unroll
            for (int nt = 0; nt < 8; nt++) {
                mma_f16(sacc[nt], qa_h[j], bf[nt]);
                mma_f16(sacc[nt], qa_l[j], bf[nt]);
            }
        }

        // ---- online softmax ----
        float mx0 = -1e30f, mx1 = -1e30f;
#pragma unroll
        for (int nt = 0; nt < 8; nt++) {
            mx0 = fmaxf(mx0, fmaxf(sacc[nt][0], sacc[nt][1]));
            mx1 = fmaxf(mx1, fmaxf(sacc[nt][2], sacc[nt][3]));
        }
        mx0 = fmaxf(mx0, __shfl_xor_sync(0xffffffffu, mx0, 1));
        mx0 = fmaxf(mx0, __shfl_xor_sync(0xffffffffu, mx0, 2));
        mx1 = fmaxf(mx1, __shfl_xor_sync(0xffffffffu, mx1, 1));
        mx1 = fmaxf(mx1, __shfl_xor_sync(0xffffffffu, mx1, 2));

        const float mn0 = fmaxf(mrow0, mx0), mn1 = fmaxf(mrow1, mx1);
        const float corr0 = __expf(mrow0 - mn0), corr1 = __expf(mrow1 - mn1);
        mrow0 = mn0; mrow1 = mn1;

        float sum0 = 0.f, sum1 = 0.f;
#pragma unroll
        for (int nt = 0; nt < 8; nt++) {
            sacc[nt][0] = __expf(sacc[nt][0] - mn0);
            sacc[nt][1] = __expf(sacc[nt][1] - mn0);
            sacc[nt][2] = __expf(sacc[nt][2] - mn1);
            sacc[nt][3] = __expf(sacc[nt][3] - mn1);
            sum0 += sacc[nt][0] + sacc[nt][1];
            sum1 += sacc[nt][2] + sacc[nt][3];
        }
        lrow0 = lrow0 * corr0 + sum0;
        lrow1 = lrow1 * corr1 + sum1;
#pragma unroll
        for (int ot = 0; ot < 12; ot++) {
            oacc[ot][0] *= corr0; oacc[ot][1] *= corr0;
            oacc[ot][2] *= corr1; oacc[ot][3] *= corr1;
        }

        // ---- O += P V (P split hi/lo fp16, V single) ----
#pragma unroll
        for (int jj = 0; jj < 4; jj++) {
            uint32_t pa_h[4], pa_l[4];
            {
                const float p00 = sacc[2*jj][0],   p01 = sacc[2*jj][1];
                const float p10 = sacc[2*jj][2],   p11 = sacc[2*jj][3];
                const float p20 = sacc[2*jj+1][0], p21 = sacc[2*jj+1][1];
                const float p30 = sacc[2*jj+1][2], p31 = sacc[2*jj+1][3];
                pa_h[0] = pk_h2(p00, p01);
                pa_h[1] = pk_h2(p10, p11);
                pa_h[2] = pk_h2(p20, p21);
                pa_h[3] = pk_h2(p30, p31);
                pa_l[0] = pk_h2(p00 - __half2float(__float2half(p00)),
                                p01 - __half2float(__float2half(p01)));
                pa_l[1] = pk_h2(p10 - __half2float(__float2half(p10)),
                                p11 - __half2float(__float2half(p11)));
                pa_l[2] = pk_h2(p20 - __half2float(__float2half(p20)),
                                p21 - __half2float(__float2half(p21)));
                pa_l[3] = pk_h2(p30 - __half2float(__float2half(p30)),
                                p31 - __half2float(__float2half(p31)));
            }
#pragma unroll
            for (int np = 0; np < 6; np++) {
                uint32_t vf[2][2];
                const int sel = lane >> 3;
                const uint32_t row = (uint32_t)(jj * 16 + ((sel & 1) ? 8 : 0) + (lane & 7));
                const uint32_t col = (uint32_t)(np * 16 + ((sel & 2) ? 8 : 0));
                const uint32_t ad = vb + row * FSTRIDE + col * 2;
                LDMX4T(vf[0][0], vf[0][1], vf[1][0], vf[1][1], ad);
                mma_f16(oacc[2*np],   pa_h, vf[0]);
                mma_f16(oacc[2*np],   pa_l, vf[0]);
                mma_f16(oacc[2*np+1], pa_h, vf[1]);
                mma_f16(oacc[2*np+1], pa_l, vf[1]);
            }
        }
        __syncthreads();
    }

    // ---- finalize ----
    lrow0 += __shfl_xor_sync(0xffffffffu, lrow0, 1);
    lrow0 += __shfl_xor_sync(0xffffffffu, lrow0, 2);
    lrow1 += __shfl_xor_sync(0xffffffffu, lrow1, 1);
    lrow1 += __shfl_xor_sync(0xffffffffu, lrow1, 2);
    const float inv0 = 1.f / lrow0, inv1 = 1.f / lrow1;

    const int nrow = m0 + wid * 16 + g;
    float* o0 = g_ctx + (size_t)(b * N_ + nrow) * HDH + h * DH_;
    float* o1 = g_ctx + (size_t)(b * N_ + nrow + 8) * HDH + h * DH_;
#pragma unroll
    for (int ot = 0; ot < 12; ot++) {
        const int d0 = ot * 8 + tg * 2;
        *(float2*)(o0 + d0) = make_float2(oacc[ot][0] * inv0, oacc[ot][1] * inv0);
        *(float2*)(o1 + d0) = make_float2(oacc[ot][2] * inv1, oacc[ot][3] * inv1);
    }
}

// ------------------------------------------------------------------
extern "C" void kernel_launch(void* const* d_in, const int* in_sizes, int n_in,
                              void* d_out, int out_size) {
    const float* x    = (const float*)d_in[0];
    const float* f1   = (const float*)d_in[1];
    const float* f2   = (const float*)d_in[2];
    const float* f3   = (const float*)d_in[3];
    const float* Wqkv = (const float*)d_in[4];
    const float* Wout = (const float*)d_in[5];
    const float* bout = (const float*)d_in[6];
    float* out = (float*)d_out;

    float *qkv, *ctx;
    __half *xhi, *xlo, *chi, *clo, *wqt, *wot;
    cudaGetSymbolAddress((void**)&qkv, g_qkv);
    cudaGetSymbolAddress((void**)&ctx, g_ctx);
    cudaGetSymbolAddress((void**)&xhi, g_xhi);
    cudaGetSymbolAddress((void**)&xlo, g_xlo);
    cudaGetSymbolAddress((void**)&chi, g_chi);
    cudaGetSymbolAddress((void**)&clo, g_clo);
    cudaGetSymbolAddress((void**)&wqt, g_wqt);
    cudaGetSymbolAddress((void**)&wot, g_wot);

    cudaFuncSetAttribute(gemm_mma, cudaFuncAttributeMaxDynamicSharedMemorySize, GEMM_SMEM);
    cudaFuncSetAttribute(flash_mma, cudaFuncAttributeMaxDynamicSharedMemorySize, FLASH_SMEM);

    // 1) x -> fp16 hi/lo; weights -> transposed fp16
    cvt_hilo<<<(M_ * DIM_ / 4 + 255) / 256, 256>>>(x, xhi, xlo, M_ * DIM_ / 4);
    transpose_f16<<<dim3(QKV3 / 32, DIM_ / 32), dim3(32, 8)>>>(Wqkv, wqt, DIM_, QKV3);
    transpose_f16<<<dim3(HDH / 32, HDH / 32), dim3(32, 8)>>>(Wout, wot, HDH, HDH);

    // 2) QKV GEMM
    gemm_mma<<<dim3(QKV3 / 128, M_ / 128), 256, GEMM_SMEM>>>(
        xhi, xlo, wqt, nullptr, qkv, QKV3, DIM_);

    // 3) RoPE -> q hi/lo (pre-scaled), k/v fp16
    rope_kernel<<<3 * B_ * H_ * N_ * DH_ / 256, 256>>>(f1, f2, f3);

    // 4) Flash attention
    flash_mma<<<dim3(N_ / FBM, B_ * H_), 256, FLASH_SMEM>>>();

    // 5) ctx -> fp16 hi/lo, output GEMM + bias
    cvt_hilo<<<(M_ * HDH / 4 + 255) / 256, 256>>>(ctx, chi, clo, M_ * HDH / 4);
    gemm_mma<<<dim3(HDH / 128, M_ / 128), 256, GEMM_SMEM>>>(
        chi, clo, wot, bout, out, HDH, HDH);
}

// round 7
// speedup vs baseline: 5.3373x; 1.1511x over previous
#include <cuda_runtime.h>
#include <cuda_fp16.h>
#include <cstdint>

#define B_    4
#define N_    2048
#define DIM_  1536
#define H_    16
#define DH_   96
#define QKV3  4608      // 3*H*DH
#define HDH   1536      // H*DH
#define M_    (B_*N_)   // 8192
#define SCALE_ 0.10206207261596575f  // 96^-0.5

// ---------------- scratch (no allocations allowed) ----------------
__device__ float g_qkv[(size_t)M_ * QKV3];           // 151 MB
__device__ float g_ctx[(size_t)M_ * HDH];            // 50 MB

__device__ __half g_xhi[(size_t)M_ * DIM_];
__device__ __half g_xlo[(size_t)M_ * DIM_];
__device__ __half g_chi[(size_t)M_ * HDH];
__device__ __half g_clo[(size_t)M_ * HDH];
__device__ __half g_wqt[(size_t)QKV3 * DIM_];        // W^T [N,K] single fp16
__device__ __half g_wot[(size_t)HDH * HDH];

// q hi/lo; k, v single fp16. layout [b*H + h][n][d]; q pre-scaled
#define PER_T ((size_t)B_ * H_ * N_ * DH_)
__device__ __half g_qh[PER_T];
__device__ __half g_ql[PER_T];
__device__ __half g_kk[PER_T];
__device__ __half g_vv[PER_T];

// ================= helpers (sm_80+ only) ==========================
__device__ __forceinline__ uint32_t smem_u32(const void* p) {
    uint32_t a;
    asm("{ .reg .u64 t; cvta.to.shared.u64 t, %1; cvt.u32.u64 %0, t; }"
        : "=r"(a) : "l"(p));
    return a;
}
#define CP_ASYNC16(saddr, gptr) \
    asm volatile("cp.async.cg.shared.global [%0], [%1], 16;" :: "r"(saddr), "l"(gptr))
#define CP_COMMIT() asm volatile("cp.async.commit_group;" ::: "memory")
#define CP_WAIT(n)  asm volatile("cp.async.wait_group %0;" :: "n"(n) : "memory")

#define LDMX4(r0,r1,r2,r3,addr) \
    asm volatile("ldmatrix.sync.aligned.m8n8.x4.shared.b16 {%0,%1,%2,%3}, [%4];" \
        : "=r"(r0),"=r"(r1),"=r"(r2),"=r"(r3) : "r"(addr))
#define LDMX4T(r0,r1,r2,r3,addr) \
    asm volatile("ldmatrix.sync.aligned.m8n8.x4.trans.shared.b16 {%0,%1,%2,%3}, [%4];" \
        : "=r"(r0),"=r"(r1),"=r"(r2),"=r"(r3) : "r"(addr))

__device__ __forceinline__ void mma_f16(float* c, const uint32_t* a, const uint32_t* b) {
    asm volatile(
        "mma.sync.aligned.m16n8k16.row.col.f32.f16.f16.f32 "
        "{%0,%1,%2,%3}, {%4,%5,%6,%7}, {%8,%9}, {%0,%1,%2,%3};"
        : "+f"(c[0]), "+f"(c[1]), "+f"(c[2]), "+f"(c[3])
        : "r"(a[0]), "r"(a[1]), "r"(a[2]), "r"(a[3]), "r"(b[0]), "r"(b[1]));
}
__device__ __forceinline__ uint32_t pk_h2(float a, float b) {
    __half2 t = __floats2half2_rn(a, b);
    return *(uint32_t*)&t;
}

// ====== 2-term fp16 mma.sync GEMM: C = (Ah+Al) @ Wt^T (+bias) =====
// Ah/Al [M,K] fp16 row-major; Wt [N,K] fp16 row-major. 3 smem tiles/stage.
// Fragments via ldmatrix (stride-80 rows are bank-clean for 8-row phases).
#define GS_STRIDE 80            // 32 fp16 = 64 B data + 16 B pad
#define GS_TILE   10240         // 128 rows * 80 B
#define GS_STAGE  30720         // Ah, Al, W tiles
#define GEMM_SMEM (2 * GS_STAGE)

__global__ void __launch_bounds__(256, 2)
gemm_mma(const __half* __restrict__ Ahi, const __half* __restrict__ Alo,
         const __half* __restrict__ Wt,
         const float* __restrict__ bias, float* __restrict__ C, int N, int K) {
    extern __shared__ char sm_[];
    const uint32_t sb = smem_u32(sm_);
    const int tid = threadIdx.x;
    const int wid = tid >> 5, lane = tid & 31;
    const int g = lane >> 2, tg = lane & 3;
    const int wm = wid & 3, wn = wid >> 2;
    const int brow = blockIdx.y * 128;
    const int bcol = blockIdx.x * 128;

    // ldmatrix lane addressing
    const int lane7 = lane & 7, sel = lane >> 3;
    // A tiles in T0(r0,c0) T1(r+8,c0) T2(r0,c+8) T3(r+8,c+8) order
    const uint32_t a_rowadd = (uint32_t)(lane7 + ((sel & 1) ? 8 : 0));
    const uint32_t a_colb   = (uint32_t)(((sel >> 1) ? 8 : 0) * 2);
    // B tiles: T0(n0,k0) T1(n0,k+8) T2(n+8,k0) T3(n+8,k+8) (flash-validated order)
    const uint32_t b_rowadd = (uint32_t)(lane7 + ((sel & 2) ? 8 : 0));
    const uint32_t b_colb   = (uint32_t)(((sel & 1) ? 8 : 0) * 2);

    float acc[2][8][4];
#pragma unroll
    for (int mt = 0; mt < 2; mt++)
#pragma unroll
        for (int nt = 0; nt < 8; nt++)
#pragma unroll
            for (int i = 0; i < 4; i++) acc[mt][nt][i] = 0.f;

    const int nst = K / 32;

    auto load_stage = [&](int s) {
        const uint32_t base = sb + (uint32_t)(s & 1) * GS_STAGE;
        const int k0 = s * 32;
#pragma unroll
        for (int i = 0; i < 6; i++) {
            const int idx = tid + i * 256;
            const int tile = idx >> 9;           // 0..2
            const int w = idx & 511;
            const int r = w >> 2, c = w & 3;
            const uint32_t so = base + (uint32_t)tile * GS_TILE +
                                (uint32_t)r * GS_STRIDE + (uint32_t)c * 16;
            const char* gp;
            if (tile == 0)      gp = (const char*)Ahi + ((size_t)(brow + r) * K + k0 + c * 8) * 2;
            else if (tile == 1) gp = (const char*)Alo + ((size_t)(brow + r) * K + k0 + c * 8) * 2;
            else                gp = (const char*)Wt  + ((size_t)(bcol + r) * K + k0 + c * 8) * 2;
            CP_ASYNC16(so, gp);
        }
    };

    load_stage(0); CP_COMMIT();

    for (int s = 0; s < nst; s++) {
        if (s + 1 < nst) { load_stage(s + 1); CP_COMMIT(); CP_WAIT(1); }
        else             { CP_WAIT(0); }
        __syncthreads();

        const uint32_t base = sb + (uint32_t)(s & 1) * GS_STAGE;
#pragma unroll
        for (int kk = 0; kk < 2; kk++) {
            const uint32_t kb = (uint32_t)(kk * 16) * 2;
            uint32_t ah[2][4], al[2][4], bw[8][2];
#pragma unroll
            for (int mt = 0; mt < 2; mt++) {
                const uint32_t ar = base + (uint32_t)(wm * 32 + mt * 16 + a_rowadd) * GS_STRIDE
                                  + kb + a_colb;
                LDMX4(ah[mt][0], ah[mt][1], ah[mt][2], ah[mt][3], ar);
                LDMX4(al[mt][0], al[mt][1], al[mt][2], al[mt][3], ar + GS_TILE);
            }
#pragma unroll
            for (int nb = 0; nb < 4; nb++) {
                const uint32_t br = base + 2 * GS_TILE
                                  + (uint32_t)(wn * 64 + nb * 16 + b_rowadd) * GS_STRIDE
                                  + kb + b_colb;
                LDMX4(bw[2*nb][0], bw[2*nb][1], bw[2*nb+1][0], bw[2*nb+1][1], br);
            }
#pragma unroll
            for (int mt = 0; mt < 2; mt++)
#pragma unroll
                for (int nt = 0; nt < 8; nt++) {
                    mma_f16(acc[mt][nt], ah[mt], bw[nt]);
                    mma_f16(acc[mt][nt], al[mt], bw[nt]);
                }
        }
        __syncthreads();
    }

#pragma unroll
    for (int mt = 0; mt < 2; mt++) {
        const int r0 = brow + wm * 32 + mt * 16 + g;
#pragma unroll
        for (int nt = 0; nt < 8; nt++) {
            const int c = bcol + wn * 64 + nt * 8 + tg * 2;
            float2 v0 = make_float2(acc[mt][nt][0], acc[mt][nt][1]);
            float2 v1 = make_float2(acc[mt][nt][2], acc[mt][nt][3]);
            if (bias) {
                const float b0 = bias[c], b1 = bias[c + 1];
                v0.x += b0; v0.y += b1; v1.x += b0; v1.y += b1;
            }
            *(float2*)(C + (size_t)r0 * N + c)       = v0;
            *(float2*)(C + (size_t)(r0 + 8) * N + c) = v1;
        }
    }
}

// ---------------- fp32 -> fp16 hi/lo --------------------------------
__global__ void cvt_hilo(const float* __restrict__ src,
                         __half* __restrict__ hi, __half* __restrict__ lo, int n4) {
    const int i = blockIdx.x * blockDim.x + threadIdx.x;
    if (i >= n4) return;
    const float4 v = ((const float4*)src)[i];
    const __half h0 = __float2half(v.x), h1 = __float2half(v.y);
    const __half h2 = __float2half(v.z), h3 = __float2half(v.w);
    ((__half2*)hi)[i * 2]     = __halves2half2(h0, h1);
    ((__half2*)hi)[i * 2 + 1] = __halves2half2(h2, h3);
    ((__half2*)lo)[i * 2]     = __floats2half2_rn(v.x - __half2float(h0), v.y - __half2float(h1));
    ((__half2*)lo)[i * 2 + 1] = __floats2half2_rn(v.z - __half2float(h2), v.w - __half2float(h3));
}

// W [K,N] -> W^T [N,K] single fp16
__global__ void transpose_f16(const float* __restrict__ W,
                              __half* __restrict__ Wt, int K, int N) {
    __shared__ float t[32][33];
    const int n0 = blockIdx.x * 32, k0 = blockIdx.y * 32;
    const int tx = threadIdx.x;
    for (int y = threadIdx.y; y < 32; y += 8)
        t[y][tx] = W[(size_t)(k0 + y) * N + n0 + tx];
    __syncthreads();
    for (int y = threadIdx.y; y < 32; y += 8)
        Wt[(size_t)(n0 + y) * K + k0 + tx] = __float2half(t[tx][y]);
}

// ------- RoPE + head transpose: q -> hi/lo (pre-scaled), k/v fp16 -
__global__ void rope_kernel(const float* __restrict__ f1,
                            const float* __restrict__ f2,
                            const float* __restrict__ f3) {
    const int per = B_ * H_ * N_ * DH_;
    int idx = blockIdx.x * blockDim.x + threadIdx.x;
    if (idx >= 3 * per) return;
    const int which = idx / per;
    int r = idx - which * per;
    const int d = r % DH_;  r /= DH_;
    const int n = r % N_;   r /= N_;
    const int h = r % H_;
    const int b = r / H_;

    const size_t src_row = (size_t)(b * N_ + n) * QKV3;
    const int base = which * HDH + h * DH_;
    const float t = g_qkv[src_row + base + d];

    float outv;
    if (which == 2) {
        outv = t;
    } else {
        const int c = d >> 5;
        const int j = d & 31;
        const float* f = (c == 0) ? f1 : ((c == 1) ? f2 : f3);
        const float fr = f[n * 32 + j];
        float rot;
        if (j < 16) rot = -g_qkv[src_row + base + c * 32 + j + 16];
        else        rot =  g_qkv[src_row + base + c * 32 + j - 16];
        outv = t * __cosf(fr) + rot * __sinf(fr);
        if (which == 0) outv *= SCALE_;
    }
    const size_t o = (size_t)((b * H_ + h) * N_ + n) * DH_ + d;
    if (which == 0) {
        const __half hv = __float2half(outv);
        g_qh[o] = hv;
        g_ql[o] = __float2half(outv - __half2float(hv));
    } else if (which == 1) {
        g_kk[o] = __float2half(outv);
    } else {
        g_vv[o] = __float2half(outv);
    }
}

// ---------------- Flash attention (fp16 2-term mma.sync) ----------
#define FBM    128
#define FBN    64
#define FSTRIDE 208
#define FTILE  (64 * FSTRIDE)      // 13312
#define FSTAGE (2 * FTILE)         // 26624
#define FLASH_SMEM (2 * FSTAGE)    // 53248

__global__ void __launch_bounds__(256, 1) flash_mma() {
    extern __shared__ char sm_[];
    const uint32_t sb = smem_u32(sm_);
    const int tid = threadIdx.x;
    const int wid = tid >> 5, lane = tid & 31;
    const int g = lane >> 2, tg = lane & 3;
    const int bh = blockIdx.y;
    const int b  = bh >> 4, h = bh & 15;
    const int m0 = blockIdx.x * FBM;

    const size_t tbase = (size_t)bh * N_ * DH_;

    const int qrow = m0 + wid * 16 + g;
    const char* qh = (const char*)(g_qh + tbase + (size_t)qrow * DH_);
    const char* ql = (const char*)(g_ql + tbase + (size_t)qrow * DH_);
    uint32_t qa_h[6][4], qa_l[6][4];
#pragma unroll
    for (int j = 0; j < 6; j++) {
        const int c0 = (j * 16 + tg * 2) * 2;
        qa_h[j][0] = *(const uint32_t*)(qh + c0);
        qa_h[j][1] = *(const uint32_t*)(qh + 8 * DH_ * 2 + c0);
        qa_h[j][2] = *(const uint32_t*)(qh + c0 + 16);
        qa_h[j][3] = *(const uint32_t*)(qh + 8 * DH_ * 2 + c0 + 16);
        qa_l[j][0] = *(const uint32_t*)(ql + c0);
        qa_l[j][1] = *(const uint32_t*)(ql + 8 * DH_ * 2 + c0);
        qa_l[j][2] = *(const uint32_t*)(ql + c0 + 16);
        qa_l[j][3] = *(const uint32_t*)(ql + 8 * DH_ * 2 + c0 + 16);
    }

    float oacc[12][4];
#pragma unroll
    for (int ot = 0; ot < 12; ot++)
#pragma unroll
        for (int i = 0; i < 4; i++) oacc[ot][i] = 0.f;
    float mrow0 = -1e30f, mrow1 = -1e30f, lrow0 = 0.f, lrow1 = 0.f;

    const char* srcK = (const char*)(g_kk + tbase);
    const char* srcV = (const char*)(g_vv + tbase);

    auto load_stage = [&](int s) {
        const uint32_t base = sb + (uint32_t)(s & 1) * FSTAGE;
        const int n0 = s * FBN;
#pragma unroll
        for (int i = 0; i < 6; i++) {
            const int idx = tid + i * 256;
            const int tile = idx / 768;
            const int w = idx % 768;
            const int r = w / 12, c = w % 12;
            const uint32_t so = base + (uint32_t)tile * FTILE +
                                (uint32_t)r * FSTRIDE + (uint32_t)c * 16;
            const size_t go = ((size_t)(n0 + r) * DH_ + c * 8) * 2;
            CP_ASYNC16(so, (tile == 0 ? srcK : srcV) + go);
        }
    };

    load_stage(0); CP_COMMIT();

    const int nkv = N_ / FBN;   // 32
    for (int s = 0; s < nkv; s++) {
        if (s + 1 < nkv) { load_stage(s + 1); CP_COMMIT(); CP_WAIT(1); }
        else             { CP_WAIT(0); }
        __syncthreads();

        const uint32_t kb = sb + (uint32_t)(s & 1) * FSTAGE;
        const uint32_t vb = kb + FTILE;

        float sacc[8][4];
#pragma unroll
        for (int nt = 0; nt < 8; nt++)
#pragma unroll
            for (int i = 0; i < 4; i++) sacc[nt][i] = 0.f;

#pragma unroll
        for (int j = 0; j < 6; j++) {
            uint32_t bf[8][2];
#pragma unroll
            for (int np = 0; np < 4; np++) {
                const int sel = lane >> 3;
                const uint32_t row = (uint32_t)(np * 16 + ((sel & 2) ? 8 : 0) + (lane & 7));
                const uint32_t col = (uint32_t)(j * 16 + ((sel & 1) ? 8 : 0));
                const uint32_t ad = kb + row * FSTRIDE + col * 2;
                LDMX4(bf[2*np][0], bf[2*np][1], bf[2*np+1][0], bf[2*np+1][1], ad);
            }
#pragma unroll
            for (int nt = 0; nt < 8; nt++) {
                mma_f16(sacc[nt], qa_h[j], bf[nt]);
                mma_f16(sacc[nt], qa_l[j], bf[nt]);
            }
        }

        float mx0 = -1e30f, mx1 = -1e30f;
#pragma unroll
        for (int nt = 0; nt < 8; nt++) {
            mx0 = fmaxf(mx0, fmaxf(sacc[nt][0], sacc[nt][1]));
            mx1 = fmaxf(mx1, fmaxf(sacc[nt][2], sacc[nt][3]));
        }
        mx0 = fmaxf(mx0, __shfl_xor_sync(0xffffffffu, mx0, 1));
        mx0 = fmaxf(mx0, __shfl_xor_sync(0xffffffffu, mx0, 2));
        mx1 = fmaxf(mx1, __shfl_xor_sync(0xffffffffu, mx1, 1));
        mx1 = fmaxf(mx1, __shfl_xor_sync(0xffffffffu, mx1, 2));

        const float mn0 = fmaxf(mrow0, mx0), mn1 = fmaxf(mrow1, mx1);
        const float corr0 = __expf(mrow0 - mn0), corr1 = __expf(mrow1 - mn1);
        mrow0 = mn0; mrow1 = mn1;

        float sum0 = 0.f, sum1 = 0.f;
#pragma unroll
        for (int nt = 0; nt < 8; nt++) {
            sacc[nt][0] = __expf(sacc[nt][0] - mn0);
            sacc[nt][1] = __expf(sacc[nt][1] - mn0);
            sacc[nt][2] = __expf(sacc[nt][2] - mn1);
            sacc[nt][3] = __expf(sacc[nt][3] - mn1);
            sum0 += sacc[nt][0] + sacc[nt][1];
            sum1 += sacc[nt][2] + sacc[nt][3];
        }
        lrow0 = lrow0 * corr0 + sum0;
        lrow1 = lrow1 * corr1 + sum1;
#pragma unroll
        for (int ot = 0; ot < 12; ot++) {
            oacc[ot][0] *= corr0; oacc[ot][1] *= corr0;
            oacc[ot][2] *= corr1; oacc[ot][3] *= corr1;
        }

#pragma unroll
        for (int jj = 0; jj < 4; jj++) {
            uint32_t pa_h[4], pa_l[4];
            {
                const float p00 = sacc[2*jj][0],   p01 = sacc[2*jj][1];
                const float p10 = sacc[2*jj][2],   p11 = sacc[2*jj][3];
                const float p20 = sacc[2*jj+1][0], p21 = sacc[2*jj+1][1];
                const float p30 = sacc[2*jj+1][2], p31 = sacc[2*jj+1][3];
                pa_h[0] = pk_h2(p00, p01);
                pa_h[1] = pk_h2(p10, p11);
                pa_h[2] = pk_h2(p20, p21);
                pa_h[3] = pk_h2(p30, p31);
                pa_l[0] = pk_h2(p00 - __half2float(__float2half(p00)),
                                p01 - __half2float(__float2half(p01)));
                pa_l[1] = pk_h2(p10 - __half2float(__float2half(p10)),
                                p11 - __half2float(__float2half(p11)));
                pa_l[2] = pk_h2(p20 - __half2float(__float2half(p20)),
                                p21 - __half2float(__float2half(p21)));
                pa_l[3] = pk_h2(p30 - __half2float(__float2half(p30)),
                                p31 - __half2float(__float2half(p31)));
            }
#pragma unroll
            for (int np = 0; np < 6; np++) {
                uint32_t vf[2][2];
                const int sel = lane >> 3;
                const uint32_t row = (uint32_t)(jj * 16 + ((sel & 1) ? 8 : 0) + (lane & 7));
                const uint32_t col = (uint32_t)(np * 16 + ((sel & 2) ? 8 : 0));
                const uint32_t ad = vb + row * FSTRIDE + col * 2;
                LDMX4T(vf[0][0], vf[0][1], vf[1][0], vf[1][1], ad);
                mma_f16(oacc[2*np],   pa_h, vf[0]);
                mma_f16(oacc[2*np],   pa_l, vf[0]);
                mma_f16(oacc[2*np+1], pa_h, vf[1]);
                mma_f16(oacc[2*np+1], pa_l, vf[1]);
            }
        }
        __syncthreads();
    }

    lrow0 += __shfl_xor_sync(0xffffffffu, lrow0, 1);
    lrow0 += __shfl_xor_sync(0xffffffffu, lrow0, 2);
    lrow1 += __shfl_xor_sync(0xffffffffu, lrow1, 1);
    lrow1 += __shfl_xor_sync(0xffffffffu, lrow1, 2);
    const float inv0 = 1.f / lrow0, inv1 = 1.f / lrow1;

    const int nrow = m0 + wid * 16 + g;
    float* o0 = g_ctx + (size_t)(b * N_ + nrow) * HDH + h * DH_;
    float* o1 = g_ctx + (size_t)(b * N_ + nrow + 8) * HDH + h * DH_;
#pragma unroll
    for (int ot = 0; ot < 12; ot++) {
        const int d0 = ot * 8 + tg * 2;
        *(float2*)(o0 + d0) = make_float2(oacc[ot][0] * inv0, oacc[ot][1] * inv0);
        *(float2*)(o1 + d0) = make_float2(oacc[ot][2] * inv1, oacc[ot][3] * inv1);
    }
}

// ------------------------------------------------------------------
extern "C" void kernel_launch(void* const* d_in, const int* in_sizes, int n_in,
                              void* d_out, int out_size) {
    const float* x    = (const float*)d_in[0];
    const float* f1   = (const float*)d_in[1];
    const float* f2   = (const float*)d_in[2];
    const float* f3   = (const float*)d_in[3];
    const float* Wqkv = (const float*)d_in[4];
    const float* Wout = (const float*)d_in[5];
    const float* bout = (const float*)d_in[6];
    float* out = (float*)d_out;

    float *qkv, *ctx;
    __half *xhi, *xlo, *chi, *clo, *wqt, *wot;
    cudaGetSymbolAddress((void**)&qkv, g_qkv);
    cudaGetSymbolAddress((void**)&ctx, g_ctx);
    cudaGetSymbolAddress((void**)&xhi, g_xhi);
    cudaGetSymbolAddress((void**)&xlo, g_xlo);
    cudaGetSymbolAddress((void**)&chi, g_chi);
    cudaGetSymbolAddress((void**)&clo, g_clo);
    cudaGetSymbolAddress((void**)&wqt, g_wqt);
    cudaGetSymbolAddress((void**)&wot, g_wot);

    cudaFuncSetAttribute(gemm_mma, cudaFuncAttributeMaxDynamicSharedMemorySize, GEMM_SMEM);
    cudaFuncSetAttribute(flash_mma, cudaFuncAttributeMaxDynamicSharedMemorySize, FLASH_SMEM);

    // 1) x -> fp16 hi/lo; weights -> transposed fp16
    cvt_hilo<<<(M_ * DIM_ / 4 + 255) / 256, 256>>>(x, xhi, xlo, M_ * DIM_ / 4);
    transpose_f16<<<dim3(QKV3 / 32, DIM_ / 32), dim3(32, 8)>>>(Wqkv, wqt, DIM_, QKV3);
    transpose_f16<<<dim3(HDH / 32, HDH / 32), dim3(32, 8)>>>(Wout, wot, HDH, HDH);

    // 2) QKV GEMM
    gemm_mma<<<dim3(QKV3 / 128, M_ / 128), 256, GEMM_SMEM>>>(
        xhi, xlo, wqt, nullptr, qkv, QKV3, DIM_);

    // 3) RoPE -> q hi/lo (pre-scaled), k/v fp16
    rope_kernel<<<3 * B_ * H_ * N_ * DH_ / 256, 256>>>(f1, f2, f3);

    // 4) Flash attention
    flash_mma<<<dim3(N_ / FBM, B_ * H_), 256, FLASH_SMEM>>>();

    // 5) ctx -> fp16 hi/lo, output GEMM + bias
    cvt_hilo<<<(M_ * HDH / 4 + 255) / 256, 256>>>(ctx, chi, clo, M_ * HDH / 4);
    gemm_mma<<<dim3(HDH / 128, M_ / 128), 256, GEMM_SMEM>>>(
        chi, clo, wot, bout, out, HDH, HDH);
}

// round 8
// speedup vs baseline: 5.8532x; 1.0967x over previous
#include <cuda_runtime.h>
#include <cuda_fp16.h>
#include <cstdint>

#define B_    4
#define N_    2048
#define DIM_  1536
#define H_    16
#define DH_   96
#define QKV3  4608      // 3*H*DH
#define HDH   1536      // H*DH
#define M_    (B_*N_)   // 8192
#define SCALE_ 0.10206207261596575f  // 96^-0.5

// ---------------- scratch (no allocations allowed) ----------------
__device__ __half g_xhi[(size_t)M_ * DIM_];
__device__ __half g_xlo[(size_t)M_ * DIM_];
__device__ __half g_chi[(size_t)M_ * HDH];
__device__ __half g_clo[(size_t)M_ * HDH];
__device__ __half g_wqt[(size_t)QKV3 * DIM_];        // W^T [N,K] single fp16
__device__ __half g_wot[(size_t)HDH * HDH];

// q hi/lo; k, v single fp16. layout [b*H + h][n][d]; q pre-scaled
#define PER_T ((size_t)B_ * H_ * N_ * DH_)
__device__ __half g_qh[PER_T];
__device__ __half g_ql[PER_T];
__device__ __half g_kk[PER_T];
__device__ __half g_vv[PER_T];

// cos/sin table: [chunk(3)][n(2048)][j(32)] -> (cos f, sin f)
__device__ float2 g_cs[3 * N_ * 32];

// ================= helpers (sm_80+ only) ==========================
__device__ __forceinline__ uint32_t smem_u32(const void* p) {
    uint32_t a;
    asm("{ .reg .u64 t; cvta.to.shared.u64 t, %1; cvt.u32.u64 %0, t; }"
        : "=r"(a) : "l"(p));
    return a;
}
#define CP_ASYNC16(saddr, gptr) \
    asm volatile("cp.async.cg.shared.global [%0], [%1], 16;" :: "r"(saddr), "l"(gptr))
#define CP_COMMIT() asm volatile("cp.async.commit_group;" ::: "memory")
#define CP_WAIT(n)  asm volatile("cp.async.wait_group %0;" :: "n"(n) : "memory")

#define LDMX4(r0,r1,r2,r3,addr) \
    asm volatile("ldmatrix.sync.aligned.m8n8.x4.shared.b16 {%0,%1,%2,%3}, [%4];" \
        : "=r"(r0),"=r"(r1),"=r"(r2),"=r"(r3) : "r"(addr))
#define LDMX4T(r0,r1,r2,r3,addr) \
    asm volatile("ldmatrix.sync.aligned.m8n8.x4.trans.shared.b16 {%0,%1,%2,%3}, [%4];" \
        : "=r"(r0),"=r"(r1),"=r"(r2),"=r"(r3) : "r"(addr))

__device__ __forceinline__ void mma_f16(float* c, const uint32_t* a, const uint32_t* b) {
    asm volatile(
        "mma.sync.aligned.m16n8k16.row.col.f32.f16.f16.f32 "
        "{%0,%1,%2,%3}, {%4,%5,%6,%7}, {%8,%9}, {%0,%1,%2,%3};"
        : "+f"(c[0]), "+f"(c[1]), "+f"(c[2]), "+f"(c[3])
        : "r"(a[0]), "r"(a[1]), "r"(a[2]), "r"(a[3]), "r"(b[0]), "r"(b[1]));
}
__device__ __forceinline__ uint32_t pk_h2(float a, float b) {
    __half2 t = __floats2half2_rn(a, b);
    return *(uint32_t*)&t;
}

// ---- cos/sin table init --------------------------------------------
__global__ void cs_init(const float* __restrict__ f1, const float* __restrict__ f2,
                        const float* __restrict__ f3) {
    const int i = blockIdx.x * 256 + threadIdx.x;
    if (i >= 3 * N_ * 32) return;
    const int chunk = i / (N_ * 32);
    const int rem = i - chunk * (N_ * 32);
    const float* f = (chunk == 0) ? f1 : ((chunk == 1) ? f2 : f3);
    const float fr = f[rem];
    g_cs[i] = make_float2(cosf(fr), sinf(fr));
}

// ====== 2-term fp16 mma.sync GEMM =================================
// ROPE=0: C = (Ah+Al)@Wt^T + bias (fp32 out).
// ROPE=1: QKV gemm; epilogue applies RoPE (via g_cs) + head transpose,
//         writes g_qh/g_ql (scaled), g_kk, g_vv fp16 directly.
#define GS_STRIDE 80
#define GS_TILE   10240
#define GS_STAGE  30720
#define GEMM_SMEM (2 * GS_STAGE)

template <int ROPE>
__global__ void __launch_bounds__(256, 2)
gemm_mma(const __half* __restrict__ Ahi, const __half* __restrict__ Alo,
         const __half* __restrict__ Wt,
         const float* __restrict__ bias, float* __restrict__ C, int N, int K) {
    extern __shared__ char sm_[];
    const uint32_t sb = smem_u32(sm_);
    const int tid = threadIdx.x;
    const int wid = tid >> 5, lane = tid & 31;
    const int g = lane >> 2, tg = lane & 3;
    const int wm = wid & 3, wn = wid >> 2;
    const int brow = blockIdx.y * 128;
    const int bcol = blockIdx.x * 128;

    const int lane7 = lane & 7, sel = lane >> 3;
    const uint32_t a_rowadd = (uint32_t)(lane7 + ((sel & 1) ? 8 : 0));
    const uint32_t a_colb   = (uint32_t)(((sel >> 1) ? 8 : 0) * 2);
    const uint32_t b_rowadd = (uint32_t)(lane7 + ((sel & 2) ? 8 : 0));
    const uint32_t b_colb   = (uint32_t)(((sel & 1) ? 8 : 0) * 2);

    float acc[2][8][4];
#pragma unroll
    for (int mt = 0; mt < 2; mt++)
#pragma unroll
        for (int nt = 0; nt < 8; nt++)
#pragma unroll
            for (int i = 0; i < 4; i++) acc[mt][nt][i] = 0.f;

    const int nst = K / 32;

    auto load_stage = [&](int s) {
        const uint32_t base = sb + (uint32_t)(s & 1) * GS_STAGE;
        const int k0 = s * 32;
#pragma unroll
        for (int i = 0; i < 6; i++) {
            const int idx = tid + i * 256;
            const int tile = idx >> 9;
            const int w = idx & 511;
            const int r = w >> 2, c = w & 3;
            const uint32_t so = base + (uint32_t)tile * GS_TILE +
                                (uint32_t)r * GS_STRIDE + (uint32_t)c * 16;
            const char* gp;
            if (tile == 0)      gp = (const char*)Ahi + ((size_t)(brow + r) * K + k0 + c * 8) * 2;
            else if (tile == 1) gp = (const char*)Alo + ((size_t)(brow + r) * K + k0 + c * 8) * 2;
            else                gp = (const char*)Wt  + ((size_t)(bcol + r) * K + k0 + c * 8) * 2;
            CP_ASYNC16(so, gp);
        }
    };

    load_stage(0); CP_COMMIT();

    for (int s = 0; s < nst; s++) {
        if (s + 1 < nst) { load_stage(s + 1); CP_COMMIT(); CP_WAIT(1); }
        else             { CP_WAIT(0); }
        __syncthreads();

        const uint32_t base = sb + (uint32_t)(s & 1) * GS_STAGE;
#pragma unroll
        for (int kk = 0; kk < 2; kk++) {
            const uint32_t kb = (uint32_t)(kk * 16) * 2;
            uint32_t ah[2][4], al[2][4], bw[8][2];
#pragma unroll
            for (int mt = 0; mt < 2; mt++) {
                const uint32_t ar = base + (uint32_t)(wm * 32 + mt * 16 + a_rowadd) * GS_STRIDE
                                  + kb + a_colb;
                LDMX4(ah[mt][0], ah[mt][1], ah[mt][2], ah[mt][3], ar);
                LDMX4(al[mt][0], al[mt][1], al[mt][2], al[mt][3], ar + GS_TILE);
            }
#pragma unroll
            for (int nb = 0; nb < 4; nb++) {
                const uint32_t br = base + 2 * GS_TILE
                                  + (uint32_t)(wn * 64 + nb * 16 + b_rowadd) * GS_STRIDE
                                  + kb + b_colb;
                LDMX4(bw[2*nb][0], bw[2*nb][1], bw[2*nb+1][0], bw[2*nb+1][1], br);
            }
#pragma unroll
            for (int mt = 0; mt < 2; mt++)
#pragma unroll
                for (int nt = 0; nt < 8; nt++) {
                    mma_f16(acc[mt][nt], ah[mt], bw[nt]);
                    mma_f16(acc[mt][nt], al[mt], bw[nt]);
                }
        }
        __syncthreads();
    }

    if (ROPE) {
        // which tensor does this col-tile belong to (tile never straddles)
        const int which = bcol / HDH;   // 0=q 1=k 2=v
#pragma unroll
        for (int mt = 0; mt < 2; mt++) {
#pragma unroll
            for (int hf = 0; hf < 2; hf++) {
                const int row = brow + wm * 32 + mt * 16 + g + hf * 8;
                const int bb = row >> 11, n = row & (N_ - 1);
                const int i0 = hf * 2;
                // rope pairs: ntA in {0,1,4,5} (j<16), partner ntB=ntA+2 (j+16)
#pragma unroll
                for (int pp = 0; pp < 4; pp++) {
                    const int ntA = (pp >> 1) * 4 + (pp & 1);
                    const int ntB = ntA + 2;
                    const int cA = bcol + wn * 64 + ntA * 8 + tg * 2;
                    const int cq = cA - which * HDH;
                    const int hh = cq / DH_;
                    const int dA = cq - hh * DH_;
                    const int jA = dA & 31;
                    const int chunk = dA >> 5;
                    const float a0 = acc[mt][ntA][i0], a1 = acc[mt][ntA][i0 + 1];
                    const float b0 = acc[mt][ntB][i0], b1 = acc[mt][ntB][i0 + 1];
                    float oA0, oA1, oB0, oB1;
                    if (which == 2) {
                        oA0 = a0; oA1 = a1; oB0 = b0; oB1 = b1;
                    } else {
                        const float2* csp = g_cs + (size_t)(chunk * N_ + n) * 32;
                        const float2 cA0 = csp[jA],      cA1 = csp[jA + 1];
                        const float2 cB0 = csp[jA + 16], cB1 = csp[jA + 17];
                        oA0 = a0 * cA0.x - b0 * cA0.y;   // j<16: rot = -x[d+16]
                        oA1 = a1 * cA1.x - b1 * cA1.y;
                        oB0 = b0 * cB0.x + a0 * cB0.y;   // j>=16: rot = +x[d-16]
                        oB1 = b1 * cB1.x + a1 * cB1.y;
                        if (which == 0) {
                            oA0 *= SCALE_; oA1 *= SCALE_; oB0 *= SCALE_; oB1 *= SCALE_;
                        }
                    }
                    const size_t oA = ((size_t)((bb * H_ + hh) * N_ + n)) * DH_ + dA;
                    const size_t oB = oA + 16;
                    if (which == 0) {
                        const __half hA0 = __float2half(oA0), hA1 = __float2half(oA1);
                        const __half hB0 = __float2half(oB0), hB1 = __float2half(oB1);
                        *(__half2*)(g_qh + oA) = __halves2half2(hA0, hA1);
                        *(__half2*)(g_ql + oA) =
                            __floats2half2_rn(oA0 - __half2float(hA0), oA1 - __half2float(hA1));
                        *(__half2*)(g_qh + oB) = __halves2half2(hB0, hB1);
                        *(__half2*)(g_ql + oB) =
                            __floats2half2_rn(oB0 - __half2float(hB0), oB1 - __half2float(hB1));
                    } else if (which == 1) {
                        *(__half2*)(g_kk + oA) = __floats2half2_rn(oA0, oA1);
                        *(__half2*)(g_kk + oB) = __floats2half2_rn(oB0, oB1);
                    } else {
                        *(__half2*)(g_vv + oA) = __floats2half2_rn(oA0, oA1);
                        *(__half2*)(g_vv + oB) = __floats2half2_rn(oB0, oB1);
                    }
                }
            }
        }
    } else {
#pragma unroll
        for (int mt = 0; mt < 2; mt++) {
            const int r0 = brow + wm * 32 + mt * 16 + g;
#pragma unroll
            for (int nt = 0; nt < 8; nt++) {
                const int c = bcol + wn * 64 + nt * 8 + tg * 2;
                float2 v0 = make_float2(acc[mt][nt][0], acc[mt][nt][1]);
                float2 v1 = make_float2(acc[mt][nt][2], acc[mt][nt][3]);
                const float b0 = bias[c], b1 = bias[c + 1];
                v0.x += b0; v0.y += b1; v1.x += b0; v1.y += b1;
                *(float2*)(C + (size_t)r0 * N + c)       = v0;
                *(float2*)(C + (size_t)(r0 + 8) * N + c) = v1;
            }
        }
    }
}

// ---------------- fp32 -> fp16 hi/lo ------------------------------
__global__ void cvt_hilo(const float* __restrict__ src,
                         __half* __restrict__ hi, __half* __restrict__ lo, int n4) {
    const int i = blockIdx.x * blockDim.x + threadIdx.x;
    if (i >= n4) return;
    const float4 v = ((const float4*)src)[i];
    const __half h0 = __float2half(v.x), h1 = __float2half(v.y);
    const __half h2 = __float2half(v.z), h3 = __float2half(v.w);
    ((__half2*)hi)[i * 2]     = __halves2half2(h0, h1);
    ((__half2*)hi)[i * 2 + 1] = __halves2half2(h2, h3);
    ((__half2*)lo)[i * 2]     = __floats2half2_rn(v.x - __half2float(h0), v.y - __half2float(h1));
    ((__half2*)lo)[i * 2 + 1] = __floats2half2_rn(v.z - __half2float(h2), v.w - __half2float(h3));
}

// W [K,N] -> W^T [N,K] single fp16
__global__ void transpose_f16(const float* __restrict__ W,
                              __half* __restrict__ Wt, int K, int N) {
    __shared__ float t[32][33];
    const int n0 = blockIdx.x * 32, k0 = blockIdx.y * 32;
    const int tx = threadIdx.x;
    for (int y = threadIdx.y; y < 32; y += 8)
        t[y][tx] = W[(size_t)(k0 + y) * N + n0 + tx];
    __syncthreads();
    for (int y = threadIdx.y; y < 32; y += 8)
        Wt[(size_t)(n0 + y) * K + k0 + tx] = __float2half(t[tx][y]);
}

// ---------------- Flash attention (fp16 2-term mma.sync) ----------
// Writes ctx directly as fp16 hi/lo (g_chi/g_clo).
#define FBM    128
#define FBN    64
#define FSTRIDE 208
#define FTILE  (64 * FSTRIDE)
#define FSTAGE (2 * FTILE)
#define FLASH_SMEM (2 * FSTAGE)

__global__ void __launch_bounds__(256, 1) flash_mma() {
    extern __shared__ char sm_[];
    const uint32_t sb = smem_u32(sm_);
    const int tid = threadIdx.x;
    const int wid = tid >> 5, lane = tid & 31;
    const int g = lane >> 2, tg = lane & 3;
    const int bh = blockIdx.y;
    const int b  = bh >> 4, h = bh & 15;
    const int m0 = blockIdx.x * FBM;

    const size_t tbase = (size_t)bh * N_ * DH_;

    const int qrow = m0 + wid * 16 + g;
    const char* qh = (const char*)(g_qh + tbase + (size_t)qrow * DH_);
    const char* ql = (const char*)(g_ql + tbase + (size_t)qrow * DH_);
    uint32_t qa_h[6][4], qa_l[6][4];
#pragma unroll
    for (int j = 0; j < 6; j++) {
        const int c0 = (j * 16 + tg * 2) * 2;
        qa_h[j][0] = *(const uint32_t*)(qh + c0);
        qa_h[j][1] = *(const uint32_t*)(qh + 8 * DH_ * 2 + c0);
        qa_h[j][2] = *(const uint32_t*)(qh + c0 + 16);
        qa_h[j][3] = *(const uint32_t*)(qh + 8 * DH_ * 2 + c0 + 16);
        qa_l[j][0] = *(const uint32_t*)(ql + c0);
        qa_l[j][1] = *(const uint32_t*)(ql + 8 * DH_ * 2 + c0);
        qa_l[j][2] = *(const uint32_t*)(ql + c0 + 16);
        qa_l[j][3] = *(const uint32_t*)(ql + 8 * DH_ * 2 + c0 + 16);
    }

    float oacc[12][4];
#pragma unroll
    for (int ot = 0; ot < 12; ot++)
#pragma unroll
        for (int i = 0; i < 4; i++) oacc[ot][i] = 0.f;
    float mrow0 = -1e30f, mrow1 = -1e30f, lrow0 = 0.f, lrow1 = 0.f;

    const char* srcK = (const char*)(g_kk + tbase);
    const char* srcV = (const char*)(g_vv + tbase);

    auto load_stage = [&](int s) {
        const uint32_t base = sb + (uint32_t)(s & 1) * FSTAGE;
        const int n0 = s * FBN;
#pragma unroll
        for (int i = 0; i < 6; i++) {
            const int idx = tid + i * 256;
            const int tile = idx / 768;
            const int w = idx % 768;
            const int r = w / 12, c = w % 12;
            const uint32_t so = base + (uint32_t)tile * FTILE +
                                (uint32_t)r * FSTRIDE + (uint32_t)c * 16;
            const size_t go = ((size_t)(n0 + r) * DH_ + c * 8) * 2;
            CP_ASYNC16(so, (tile == 0 ? srcK : srcV) + go);
        }
    };

    load_stage(0); CP_COMMIT();

    const int nkv = N_ / FBN;
    for (int s = 0; s < nkv; s++) {
        if (s + 1 < nkv) { load_stage(s + 1); CP_COMMIT(); CP_WAIT(1); }
        else             { CP_WAIT(0); }
        __syncthreads();

        const uint32_t kb = sb + (uint32_t)(s & 1) * FSTAGE;
        const uint32_t vb = kb + FTILE;

        float sacc[8][4];
#pragma unroll
        for (int nt = 0; nt < 8; nt++)
#pragma unroll
            for (int i = 0; i < 4; i++) sacc[nt][i] = 0.f;

#pragma unroll
        for (int j = 0; j < 6; j++) {
            uint32_t bf[8][2];
#pragma unroll
            for (int np = 0; np < 4; np++) {
                const int sel = lane >> 3;
                const uint32_t row = (uint32_t)(np * 16 + ((sel & 2) ? 8 : 0) + (lane & 7));
                const uint32_t col = (uint32_t)(j * 16 + ((sel & 1) ? 8 : 0));
                const uint32_t ad = kb + row * FSTRIDE + col * 2;
                LDMX4(bf[2*np][0], bf[2*np][1], bf[2*np+1][0], bf[2*np+1][1], ad);
            }
#pragma unroll
            for (int nt = 0; nt < 8; nt++) {
                mma_f16(sacc[nt], qa_h[j], bf[nt]);
                mma_f16(sacc[nt], qa_l[j], bf[nt]);
            }
        }

        float mx0 = -1e30f, mx1 = -1e30f;
#pragma unroll
        for (int nt = 0; nt < 8; nt++) {
            mx0 = fmaxf(mx0, fmaxf(sacc[nt][0], sacc[nt][1]));
            mx1 = fmaxf(mx1, fmaxf(sacc[nt][2], sacc[nt][3]));
        }
        mx0 = fmaxf(mx0, __shfl_xor_sync(0xffffffffu, mx0, 1));
        mx0 = fmaxf(mx0, __shfl_xor_sync(0xffffffffu, mx0, 2));
        mx1 = fmaxf(mx1, __shfl_xor_sync(0xffffffffu, mx1, 1));
        mx1 = fmaxf(mx1, __shfl_xor_sync(0xffffffffu, mx1, 2));

        const float mn0 = fmaxf(mrow0, mx0), mn1 = fmaxf(mrow1, mx1);
        const float corr0 = __expf(mrow0 - mn0), corr1 = __expf(mrow1 - mn1);
        mrow0 = mn0; mrow1 = mn1;

        float sum0 = 0.f, sum1 = 0.f;
#pragma unroll
        for (int nt = 0; nt < 8; nt++) {
            sacc[nt][0] = __expf(sacc[nt][0] - mn0);
            sacc[nt][1] = __expf(sacc[nt][1] - mn0);
            sacc[nt][2] = __expf(sacc[nt][2] - mn1);
            sacc[nt][3] = __expf(sacc[nt][3] - mn1);
            sum0 += sacc[nt][0] + sacc[nt][1];
            sum1 += sacc[nt][2] + sacc[nt][3];
        }
        lrow0 = lrow0 * corr0 + sum0;
        lrow1 = lrow1 * corr1 + sum1;
#pragma unroll
        for (int ot = 0; ot < 12; ot++) {
            oacc[ot][0] *= corr0; oacc[ot][1] *= corr0;
            oacc[ot][2] *= corr1; oacc[ot][3] *= corr1;
        }

#pragma unroll
        for (int jj = 0; jj < 4; jj++) {
            uint32_t pa_h[4], pa_l[4];
            {
                const float p00 = sacc[2*jj][0],   p01 = sacc[2*jj][1];
                const float p10 = sacc[2*jj][2],   p11 = sacc[2*jj][3];
                const float p20 = sacc[2*jj+1][0], p21 = sacc[2*jj+1][1];
                const float p30 = sacc[2*jj+1][2], p31 = sacc[2*jj+1][3];
                pa_h[0] = pk_h2(p00, p01);
                pa_h[1] = pk_h2(p10, p11);
                pa_h[2] = pk_h2(p20, p21);
                pa_h[3] = pk_h2(p30, p31);
                pa_l[0] = pk_h2(p00 - __half2float(__float2half(p00)),
                                p01 - __half2float(__float2half(p01)));
                pa_l[1] = pk_h2(p10 - __half2float(__float2half(p10)),
                                p11 - __half2float(__float2half(p11)));
                pa_l[2] = pk_h2(p20 - __half2float(__float2half(p20)),
                                p21 - __half2float(__float2half(p21)));
                pa_l[3] = pk_h2(p30 - __half2float(__float2half(p30)),
                                p31 - __half2float(__float2half(p31)));
            }
#pragma unroll
            for (int np = 0; np < 6; np++) {
                uint32_t vf[2][2];
                const int sel = lane >> 3;
                const uint32_t row = (uint32_t)(jj * 16 + ((sel & 1) ? 8 : 0) + (lane & 7));
                const uint32_t col = (uint32_t)(np * 16 + ((sel & 2) ? 8 : 0));
                const uint32_t ad = vb + row * FSTRIDE + col * 2;
                LDMX4T(vf[0][0], vf[0][1], vf[1][0], vf[1][1], ad);
                mma_f16(oacc[2*np],   pa_h, vf[0]);
                mma_f16(oacc[2*np],   pa_l, vf[0]);
                mma_f16(oacc[2*np+1], pa_h, vf[1]);
                mma_f16(oacc[2*np+1], pa_l, vf[1]);
            }
        }
        __syncthreads();
    }

    lrow0 += __shfl_xor_sync(0xffffffffu, lrow0, 1);
    lrow0 += __shfl_xor_sync(0xffffffffu, lrow0, 2);
    lrow1 += __shfl_xor_sync(0xffffffffu, lrow1, 1);
    lrow1 += __shfl_xor_sync(0xffffffffu, lrow1, 2);
    const float inv0 = 1.f / lrow0, inv1 = 1.f / lrow1;

    const int nrow = m0 + wid * 16 + g;
    const size_t ob0 = (size_t)(b * N_ + nrow) * HDH + h * DH_;
    const size_t ob1 = (size_t)(b * N_ + nrow + 8) * HDH + h * DH_;
#pragma unroll
    for (int ot = 0; ot < 12; ot++) {
        const int d0 = ot * 8 + tg * 2;
        const float f00 = oacc[ot][0] * inv0, f01 = oacc[ot][1] * inv0;
        const float f10 = oacc[ot][2] * inv1, f11 = oacc[ot][3] * inv1;
        const __half h00 = __float2half(f00), h01 = __float2half(f01);
        const __half h10 = __float2half(f10), h11 = __float2half(f11);
        *(__half2*)(g_chi + ob0 + d0) = __halves2half2(h00, h01);
        *(__half2*)(g_clo + ob0 + d0) =
            __floats2half2_rn(f00 - __half2float(h00), f01 - __half2float(h01));
        *(__half2*)(g_chi + ob1 + d0) = __halves2half2(h10, h11);
        *(__half2*)(g_clo + ob1 + d0) =
            __floats2half2_rn(f10 - __half2float(h10), f11 - __half2float(h11));
    }
}

// ------------------------------------------------------------------
extern "C" void kernel_launch(void* const* d_in, const int* in_sizes, int n_in,
                              void* d_out, int out_size) {
    const float* x    = (const float*)d_in[0];
    const float* f1   = (const float*)d_in[1];
    const float* f2   = (const float*)d_in[2];
    const float* f3   = (const float*)d_in[3];
    const float* Wqkv = (const float*)d_in[4];
    const float* Wout = (const float*)d_in[5];
    const float* bout = (const float*)d_in[6];
    float* out = (float*)d_out;

    __half *xhi, *xlo, *chi, *clo, *wqt, *wot;
    cudaGetSymbolAddress((void**)&xhi, g_xhi);
    cudaGetSymbolAddress((void**)&xlo, g_xlo);
    cudaGetSymbolAddress((void**)&chi, g_chi);
    cudaGetSymbolAddress((void**)&clo, g_clo);
    cudaGetSymbolAddress((void**)&wqt, g_wqt);
    cudaGetSymbolAddress((void**)&wot, g_wot);

    cudaFuncSetAttribute(gemm_mma<0>, cudaFuncAttributeMaxDynamicSharedMemorySize, GEMM_SMEM);
    cudaFuncSetAttribute(gemm_mma<1>, cudaFuncAttributeMaxDynamicSharedMemorySize, GEMM_SMEM);
    cudaFuncSetAttribute(flash_mma, cudaFuncAttributeMaxDynamicSharedMemorySize, FLASH_SMEM);

    // 0) cos/sin table
    cs_init<<<(3 * N_ * 32 + 255) / 256, 256>>>(f1, f2, f3);

    // 1) x -> fp16 hi/lo; weights -> transposed fp16
    cvt_hilo<<<(M_ * DIM_ / 4 + 255) / 256, 256>>>(x, xhi, xlo, M_ * DIM_ / 4);
    transpose_f16<<<dim3(QKV3 / 32, DIM_ / 32), dim3(32, 8)>>>(Wqkv, wqt, DIM_, QKV3);
    transpose_f16<<<dim3(HDH / 32, HDH / 32), dim3(32, 8)>>>(Wout, wot, HDH, HDH);

    // 2) QKV GEMM with fused RoPE + head-transpose epilogue
    gemm_mma<1><<<dim3(QKV3 / 128, M_ / 128), 256, GEMM_SMEM>>>(
        xhi, xlo, wqt, nullptr, nullptr, QKV3, DIM_);

    // 3) Flash attention (writes ctx hi/lo fp16 directly)
    flash_mma<<<dim3(N_ / FBM, B_ * H_), 256, FLASH_SMEM>>>();

    // 4) Output GEMM + bias
    gemm_mma<0><<<dim3(HDH / 128, M_ / 128), 256, GEMM_SMEM>>>(
        chi, clo, wot, bout, out, HDH, HDH);
}